// round 3
// baseline (speedup 1.0000x reference)
#include <cuda_runtime.h>
#include <cuda_bf16.h>
#include <cstdint>
#include <math.h>

// Problem constants
#define NB 64
#define NT 512
#define NF 256
#define NP 128
#define NH 256
#define NK 12
#define INV_TEMP 10.0f
#define BT (NB*NT)   // 32768

// ---------------- device scratch (no allocations allowed) ---------------------
__device__ float g_Wf[NF*NP];                       // fused encoder weight 256x128
__device__ float g_bz[NP];                          // fused encoder bias
__device__ float g_Wpc[NH*NK*NP];                   // Wp repacked (256 x 1536)
__device__ float g_z[(size_t)BT*NP];                // z_seq   (b,t,128)
__device__ float g_gi[(size_t)BT*3*NH];             // gi      (b,t,768)
__device__ float g_c[(size_t)BT*NH];                // c_seq   (b,t,256)
__device__ float g_pred[(size_t)BT*NK*NP];          // pred    (b,t,k*128+p)

// ---------------- helpers -----------------------------------------------------
__global__ void zero_loss_kernel(float* p){ if (threadIdx.x==0) *p = 0.f; }

__global__ void bz_kernel(const float* __restrict__ b_enc, const float* __restrict__ W_proj,
                          const float* __restrict__ b_proj, float* __restrict__ bz){
    int n = threadIdx.x;            // 128
    float s = b_proj[n];
    for (int e = 0; e < NF; e++) s += b_enc[e] * W_proj[e*NP + n];
    bz[n] = s;
}

// Wp (12,256,128) -> Wpc[h][k*128+p]
__global__ void repack_wp_kernel(const float* __restrict__ Wp, float* __restrict__ Wpc){
    int idx = blockIdx.x*blockDim.x + threadIdx.x;   // 12*256*128 = 393216
    if (idx >= NK*NH*NP) return;
    int p = idx & 127;
    int h = (idx >> 7) & 255;
    int k = idx >> 15;
    Wpc[h*(NK*NP) + k*NP + p] = Wp[(k*NH + h)*NP + p];
}

// ---------------- generic tiled GEMM: C = A(MxK) @ B(KxN) + bias --------------
// BM=128 BN=128 BK=16, 256 threads, 8x8 per-thread tile. M,N mult 128, K mult 16.
__global__ void __launch_bounds__(256) gemm_bias_kernel(
    const float* __restrict__ A, const float* __restrict__ Bm,
    const float* __restrict__ bias, float* __restrict__ C,
    int M, int N, int K)
{
    __shared__ float As[16][128];   // As[k][m]
    __shared__ float Bs[16][128];   // Bs[k][n]
    const int tid = threadIdx.x;
    const int m0 = blockIdx.y * 128, n0 = blockIdx.x * 128;
    const int tx = tid & 15, ty = tid >> 4;
    float acc[8][8];
#pragma unroll
    for (int i=0;i<8;i++)
#pragma unroll
        for (int j=0;j<8;j++) acc[i][j] = 0.f;

    for (int k0 = 0; k0 < K; k0 += 16) {
#pragma unroll
        for (int it = 0; it < 2; it++) {
            int idx = tid + it*256;              // 512 float4s of A tile (128x16)
            int r  = idx >> 2;
            int c4 = (idx & 3) << 2;
            const float4 v = *reinterpret_cast<const float4*>(A + (size_t)(m0+r)*K + k0 + c4);
            As[c4+0][r]=v.x; As[c4+1][r]=v.y; As[c4+2][r]=v.z; As[c4+3][r]=v.w;
        }
#pragma unroll
        for (int it = 0; it < 2; it++) {
            int idx = tid + it*256;              // 512 float4s of B tile (16x128)
            int r  = idx >> 5;
            int c4 = (idx & 31) << 2;
            *reinterpret_cast<float4*>(&Bs[r][c4]) =
                *reinterpret_cast<const float4*>(Bm + (size_t)(k0+r)*N + n0 + c4);
        }
        __syncthreads();
#pragma unroll
        for (int k = 0; k < 16; k++) {
            float a[8], b[8];
            *reinterpret_cast<float4*>(&a[0]) = *reinterpret_cast<float4*>(&As[k][ty*4]);
            *reinterpret_cast<float4*>(&a[4]) = *reinterpret_cast<float4*>(&As[k][ty*4+64]);
            *reinterpret_cast<float4*>(&b[0]) = *reinterpret_cast<float4*>(&Bs[k][tx*4]);
            *reinterpret_cast<float4*>(&b[4]) = *reinterpret_cast<float4*>(&Bs[k][tx*4+64]);
#pragma unroll
            for (int i=0;i<8;i++)
#pragma unroll
                for (int j=0;j<8;j++) acc[i][j] += a[i]*b[j];
        }
        __syncthreads();
    }
#pragma unroll
    for (int i=0;i<8;i++){
        int m = m0 + ty*4 + (i&3) + ((i>>2)<<6);
#pragma unroll
        for (int jg=0;jg<2;jg++){
            int n = n0 + tx*4 + jg*64;
            float4 v;
            v.x = acc[i][jg*4+0]; v.y = acc[i][jg*4+1];
            v.z = acc[i][jg*4+2]; v.w = acc[i][jg*4+3];
            if (bias){
                const float4 bv = *reinterpret_cast<const float4*>(bias + n);
                v.x += bv.x; v.y += bv.y; v.z += bv.z; v.w += bv.w;
            }
            *reinterpret_cast<float4*>(C + (size_t)m*N + n) = v;
        }
    }
}

// ---------------- GRU scan: 16 clusters of 8 CTAs, 4 batches per cluster ------
__device__ __forceinline__ unsigned smem_u32(const void* p){
    unsigned r;
    asm("{ .reg .u64 t; cvta.to.shared.u64 t, %1; cvt.u32.u64 %0, t; }" : "=r"(r) : "l"(p));
    return r;
}
__device__ __forceinline__ void st_cluster_f32(unsigned laddr, int rank, float v){
    unsigned raddr;
    asm volatile("mapa.shared::cluster.u32 %0, %1, %2;" : "=r"(raddr) : "r"(laddr), "r"(rank));
    asm volatile("st.shared::cluster.f32 [%0], %1;" :: "r"(raddr), "f"(v) : "memory");
}
__device__ __forceinline__ void cluster_sync_all(){
    asm volatile("barrier.cluster.arrive.aligned;" ::: "memory");
    asm volatile("barrier.cluster.wait.aligned;"   ::: "memory");
}

// smem floats: Whs[256*96] @0 | h2[2][256][4] @24576 | part[4*96*4] @26624
//              ghs[4*96] @28160 | bhn_s[32] @28544   (total 28576 floats)
#define GRU_SMEM_FLOATS 28576
#define GRU_SMEM_BYTES  (GRU_SMEM_FLOATS*4)

__global__ void __launch_bounds__(384) __cluster_dims__(8,1,1)
gru_kernel(const float* __restrict__ gi, const float* __restrict__ Wh,
           const float* __restrict__ bhn, float* __restrict__ c_out)
{
    extern __shared__ float sm[];
    float* Whs   = sm;            // [256][96]
    float* h2    = sm + 24576;    // [2][256][4]
    float* part  = sm + 26624;    // [4][96][4]
    float* ghs   = sm + 28160;    // [4][96]
    float* bhn_s = sm + 28544;    // [32]

    const int tid  = threadIdx.x;
    const int rank = blockIdx.x & 7;
    const int b0   = (blockIdx.x >> 3) * 4;
    const int u0   = rank * 32;

    // init: load Wh slice (gathered columns), zero h buffers, bhn slice
    for (int i = tid; i < 256*96; i += 384){
        int u = i / 96, c = i % 96;
        int gcol = (c >> 5)*256 + u0 + (c & 31);
        Whs[i] = Wh[u*768 + gcol];
    }
    for (int i = tid; i < 2048; i += 384) h2[i] = 0.f;
    if (tid < 32) bhn_s[tid] = bhn[u0 + tid];
    __syncthreads();
    cluster_sync_all();

    const int c  = tid % 96;
    const int q  = tid / 96;
    const int b3 = tid >> 5;      // gate phase (tid<128)
    const int ul = tid & 31;

    int cur = 0;
    for (int t = 0; t < NT; t++){
        // prefetch gi for gate phase
        float gir=0.f, giz=0.f, gin=0.f;
        if (tid < 128){
            const float* gp = gi + ((size_t)(b0+b3)*NT + t)*768;
            gir = gp[u0+ul]; giz = gp[256+u0+ul]; gin = gp[512+u0+ul];
        }

        // gh partial GEMM: 4 batches x 96 cols, split over u (q-quarter)
        {
            const float* hb = h2 + cur*1024;
            float a0=0.f,a1=0.f,a2=0.f,a3=0.f;
            const int ub = q*64;
#pragma unroll 8
            for (int uu = 0; uu < 64; uu++){
                int u = ub + uu;
                float w = Whs[u*96 + c];
                float4 h4 = *reinterpret_cast<const float4*>(hb + u*4);
                a0 += w*h4.x; a1 += w*h4.y; a2 += w*h4.z; a3 += w*h4.w;
            }
            float* pp = part + (q*96 + c)*4;
            pp[0]=a0; pp[1]=a1; pp[2]=a2; pp[3]=a3;
        }
        __syncthreads();

        // reduce quarters
        {
            int c2 = tid % 96, b2 = tid / 96;
            float s = part[(0*96+c2)*4+b2] + part[(1*96+c2)*4+b2]
                    + part[(2*96+c2)*4+b2] + part[(3*96+c2)*4+b2];
            ghs[b2*96 + c2] = s;
        }
        __syncthreads();

        // gate math + hidden update (tid<128: 4 batches x 32 units)
        int nxt = cur ^ 1;
        if (tid < 128){
            float hr = ghs[b3*96 + ul];
            float hz = ghs[b3*96 + 32 + ul];
            float hn = ghs[b3*96 + 64 + ul];
            float r  = 1.f/(1.f + expf(-(gir + hr)));
            float zz = 1.f/(1.f + expf(-(giz + hz)));
            float n  = tanhf(gin + r*(hn + bhn_s[ul]));
            float hp = h2[cur*1024 + (u0+ul)*4 + b3];
            float hnew = (1.f - zz)*n + zz*hp;
            c_out[((size_t)(b0+b3)*NT + t)*NH + (u0+ul)] = hnew;
            unsigned laddr = smem_u32(h2 + nxt*1024 + (u0+ul)*4 + b3);
#pragma unroll
            for (int r8 = 0; r8 < 8; r8++) st_cluster_f32(laddr, r8, hnew);
        }
        cluster_sync_all();
        cur = nxt;
    }
}

// ---------------- streaming-softmax contrastive loss --------------------------
// grid (4 t-tiles, 64 batches, 12 k). 256 threads, 128x128 tiles, K=128 dot dim.
// smem floats: Ps[128*129] @0 | Zs[128*129] @16512 | red[128*16] @33024
//              mrow[128]@35072 | srow[128]@35200 | sred[256]@35328  (35584 total)
#define LOSS_SMEM_FLOATS 35584
#define LOSS_SMEM_BYTES  (LOSS_SMEM_FLOATS*4)

__global__ void __launch_bounds__(256) loss_kernel(
    const float* __restrict__ pred, const float* __restrict__ z, float* __restrict__ out)
{
    extern __shared__ float sm[];
    float* Ps   = sm;             // [d][t] pad 129, pre-scaled by 1/TEMP
    float* Zs   = sm + 16512;     // [d][j] pad 129
    float* red  = sm + 33024;     // [128][16]
    float* mrow = sm + 35072;
    float* srow = sm + 35200;
    float* sred = sm + 35328;

    const int tid = threadIdx.x;
    const int tx  = tid & 15, ty = tid >> 4;
    const int t0  = blockIdx.x * 128;
    const int b   = blockIdx.y;
    const int k   = blockIdx.z + 1;
    const int Tm  = NT - k;

    // stage pred tile (transposed, scaled)
    for (int it = 0; it < 16; it++){
        int idx = tid + it*256;
        int tl  = idx >> 5;
        int c4  = (idx & 31) << 2;
        const float4 v = *reinterpret_cast<const float4*>(
            pred + ((size_t)(b*NT) + t0 + tl)*(NK*NP) + (size_t)(k-1)*NP + c4);
        Ps[(c4+0)*129 + tl] = v.x*INV_TEMP;
        Ps[(c4+1)*129 + tl] = v.y*INV_TEMP;
        Ps[(c4+2)*129 + tl] = v.z*INV_TEMP;
        Ps[(c4+3)*129 + tl] = v.w*INV_TEMP;
    }
    if (tid < 128){ mrow[tid] = -1e30f; srow[tid] = 0.f; }
    float totsum = 0.f;
    __syncthreads();

    int rowi[8], coli[8];
#pragma unroll
    for (int i=0;i<8;i++){
        rowi[i] = ty*4 + (i&3) + ((i>>2)<<6);
        coli[i] = tx*4 + (i&3) + ((i>>2)<<6);
    }

    for (int jt = 0; jt < 4; jt++){
        int j0 = jt*128;
        // stage z tile (transposed, zero-padded past sequence end)
        for (int it = 0; it < 16; it++){
            int idx = tid + it*256;
            int jl  = idx >> 5;
            int c4  = (idx & 31) << 2;
            float4 v = make_float4(0.f,0.f,0.f,0.f);
            if (k + j0 + jl < NT)
                v = *reinterpret_cast<const float4*>(
                    z + ((size_t)(b*NT) + k + j0 + jl)*NP + c4);
            Zs[(c4+0)*129 + jl] = v.x;
            Zs[(c4+1)*129 + jl] = v.y;
            Zs[(c4+2)*129 + jl] = v.z;
            Zs[(c4+3)*129 + jl] = v.w;
        }
        __syncthreads();

        float acc[8][8];
#pragma unroll
        for (int i=0;i<8;i++)
#pragma unroll
            for (int j=0;j<8;j++) acc[i][j] = 0.f;
#pragma unroll 4
        for (int d = 0; d < 128; d++){
            float a[8], bb[8];
#pragma unroll
            for (int i=0;i<4;i++){ a[i]  = Ps[d*129 + ty*4 + i];
                                   a[4+i]= Ps[d*129 + ty*4 + 64 + i]; }
#pragma unroll
            for (int j=0;j<4;j++){ bb[j]  = Zs[d*129 + tx*4 + j];
                                   bb[4+j]= Zs[d*129 + tx*4 + 64 + j]; }
#pragma unroll
            for (int i=0;i<8;i++)
#pragma unroll
                for (int j=0;j<8;j++) acc[i][j] += a[i]*bb[j];
        }

        // per-row tile max (col-masked)
#pragma unroll
        for (int i=0;i<8;i++){
            float mx = -1e30f;
#pragma unroll
            for (int j=0;j<8;j++){
                bool v = (j0 + coli[j]) < Tm;
                float x = v ? acc[i][j] : -1e30f;
                mx = fmaxf(mx, x);
            }
            red[rowi[i]*16 + tx] = mx;
        }
        __syncthreads();
        if (tid < 128){
            float mx = -1e30f;
#pragma unroll
            for (int x=0;x<16;x++) mx = fmaxf(mx, red[tid*16+x]);
            float M = fmaxf(mrow[tid], mx);
            srow[tid] *= __expf(mrow[tid] - M);
            mrow[tid] = M;
        }
        __syncthreads();
        // per-row sumexp partials + raw-logit total
#pragma unroll
        for (int i=0;i<8;i++){
            float Mr = mrow[rowi[i]];
            bool rv  = (t0 + rowi[i]) < Tm;
            float s = 0.f;
#pragma unroll
            for (int j=0;j<8;j++){
                bool cv = (j0 + coli[j]) < Tm;
                if (cv){
                    s += __expf(acc[i][j] - Mr);
                    if (rv) totsum += acc[i][j];
                }
            }
            red[rowi[i]*16 + tx] = s;
        }
        __syncthreads();
        if (tid < 128){
            float s = 0.f;
#pragma unroll
            for (int x=0;x<16;x++) s += red[tid*16+x];
            srow[tid] += s;
        }
        __syncthreads();
    }

    // block reductions: sum of lse over valid rows, sum of raw logits
    float lse = 0.f;
    if (tid < 128 && (t0 + tid) < Tm) lse = mrow[tid] + logf(srow[tid]);
    sred[tid] = lse;
    __syncthreads();
    for (int s = 128; s > 0; s >>= 1){
        if (tid < s) sred[tid] += sred[tid + s];
        __syncthreads();
    }
    float lse_sum = sred[0];
    __syncthreads();
    sred[tid] = totsum;
    __syncthreads();
    for (int s = 128; s > 0; s >>= 1){
        if (tid < s) sred[tid] += sred[tid + s];
        __syncthreads();
    }
    if (tid == 0){
        float tot = sred[0];
        float inv = 1.0f / ((float)NB * (float)Tm * (float)NK);
        float contrib = lse_sum * inv - tot * (inv / (float)Tm);
        atomicAdd(out, contrib);
    }
}

// ---------------- launch ------------------------------------------------------
extern "C" void kernel_launch(void* const* d_in, const int* in_sizes, int n_in,
                              void* d_out, int out_size)
{
    const float* x_seq  = (const float*)d_in[0];
    const float* W_enc  = (const float*)d_in[1];
    const float* b_enc  = (const float*)d_in[2];
    const float* W_proj = (const float*)d_in[3];
    const float* b_proj = (const float*)d_in[4];
    const float* Wi     = (const float*)d_in[5];
    const float* bi     = (const float*)d_in[6];
    const float* Wh     = (const float*)d_in[7];
    const float* bhn    = (const float*)d_in[8];
    const float* Wp     = (const float*)d_in[9];
    const float* bp     = (const float*)d_in[10];
    float* out = (float*)d_out;

    float *Wf, *bz, *Wpc, *zbuf, *gibuf, *cbuf, *predbuf;
    cudaGetSymbolAddress((void**)&Wf,     g_Wf);
    cudaGetSymbolAddress((void**)&bz,     g_bz);
    cudaGetSymbolAddress((void**)&Wpc,    g_Wpc);
    cudaGetSymbolAddress((void**)&zbuf,   g_z);
    cudaGetSymbolAddress((void**)&gibuf,  g_gi);
    cudaGetSymbolAddress((void**)&cbuf,   g_c);
    cudaGetSymbolAddress((void**)&predbuf,g_pred);

    cudaFuncSetAttribute(gru_kernel,  cudaFuncAttributeMaxDynamicSharedMemorySize, GRU_SMEM_BYTES);
    cudaFuncSetAttribute(loss_kernel, cudaFuncAttributeMaxDynamicSharedMemorySize, LOSS_SMEM_BYTES);

    zero_loss_kernel<<<1, 32>>>(out);
    bz_kernel<<<1, 128>>>(b_enc, W_proj, b_proj, bz);

    // Wf = W_enc @ W_proj   (256x128x256)
    gemm_bias_kernel<<<dim3(1,2), 256>>>(W_enc, W_proj, nullptr, Wf, 256, 128, 256);
    // z = x @ Wf + bz       (32768x128x256)
    gemm_bias_kernel<<<dim3(1,256), 256>>>(x_seq, Wf, bz, zbuf, BT, NP, NF);
    // gi = z @ Wi + bi      (32768x768x128)
    gemm_bias_kernel<<<dim3(6,256), 256>>>(zbuf, Wi, bi, gibuf, BT, 3*NH, NP);
    // repack Wp
    repack_wp_kernel<<<768, 512>>>(Wp, Wpc);
    // GRU scan (persistent, clustered)
    gru_kernel<<<128, 384, GRU_SMEM_BYTES>>>(gibuf, Wh, bhn, cbuf);
    // pred = c @ Wpc + bp   (32768x1536x256)
    gemm_bias_kernel<<<dim3(12,256), 256>>>(cbuf, Wpc, bp, predbuf, BT, NK*NP, NH);
    // streaming softmax loss
    loss_kernel<<<dim3(4,64,12), 256, LOSS_SMEM_BYTES>>>(predbuf, zbuf, out);
}

// round 5
// speedup vs baseline: 1.1752x; 1.1752x over previous
#include <cuda_runtime.h>
#include <cuda_bf16.h>
#include <cstdint>
#include <math.h>

// Problem constants
#define NB 64
#define NT 512
#define NF 256
#define NP 128
#define NH 256
#define NK 12
#define INV_TEMP 10.0f
#define BT (NB*NT)   // 32768

// ---------------- device scratch (no allocations allowed) ---------------------
__device__ float g_Wf[NF*NP];                       // fused encoder weight 256x128
__device__ float g_bz[NP];                          // fused encoder bias
__device__ float g_Wpc[NH*NK*NP];                   // Wp repacked (256 x 1536)
__device__ float g_z[(size_t)BT*NP];                // z_seq   (b,t,128)
__device__ float g_gi[(size_t)BT*3*NH];             // gi      (b,t,768)
__device__ float g_c[(size_t)BT*NH];                // c_seq   (b,t,256)
__device__ __align__(16) __nv_bfloat16 g_predp[(size_t)BT*NK*256]; // pred split [hi|lo]
__device__ __align__(16) __nv_bfloat16 g_zp[(size_t)BT*256];       // z    split [hi|lo]

// ---------------- helpers -----------------------------------------------------
__device__ __forceinline__ unsigned smem_u32(const void* p){
    unsigned r;
    asm("{ .reg .u64 t; cvta.to.shared.u64 t, %1; cvt.u32.u64 %0, t; }" : "=r"(r) : "l"(p));
    return r;
}

__global__ void zero_loss_kernel(float* p){ if (threadIdx.x==0) *p = 0.f; }

__global__ void bz_kernel(const float* __restrict__ b_enc, const float* __restrict__ W_proj,
                          const float* __restrict__ b_proj, float* __restrict__ bz){
    int n = threadIdx.x;            // 128
    float s = b_proj[n];
    for (int e = 0; e < NF; e++) s += b_enc[e] * W_proj[e*NP + n];
    bz[n] = s;
}

// Wp (12,256,128) -> Wpc[h][k*128+p]
__global__ void repack_wp_kernel(const float* __restrict__ Wp, float* __restrict__ Wpc){
    int idx = blockIdx.x*blockDim.x + threadIdx.x;
    if (idx >= NK*NH*NP) return;
    int p = idx & 127;
    int h = (idx >> 7) & 255;
    int k = idx >> 15;
    Wpc[h*(NK*NP) + k*NP + p] = Wp[(k*NH + h)*NP + p];
}

// z fp32 -> split bf16 [hi(128)|lo(128)]
__global__ void zpack_kernel(const float* __restrict__ z, __nv_bfloat16* __restrict__ zp){
    int idx = blockIdx.x*blockDim.x + threadIdx.x;
    if (idx >= BT*NP) return;
    int row = idx >> 7, c = idx & 127;
    float v = z[idx];
    __nv_bfloat16 h = __float2bfloat16(v);
    float l = v - __bfloat162float(h);
    zp[(size_t)row*256 + c]       = h;
    zp[(size_t)row*256 + 128 + c] = __float2bfloat16(l);
}

// ---------------- generic tiled GEMM: C = A(MxK) @ B(KxN) + bias --------------
__global__ void __launch_bounds__(256) gemm_bias_kernel(
    const float* __restrict__ A, const float* __restrict__ Bm,
    const float* __restrict__ bias, float* __restrict__ C,
    int M, int N, int K)
{
    __shared__ float As[16][128];
    __shared__ float Bs[16][128];
    const int tid = threadIdx.x;
    const int m0 = blockIdx.y * 128, n0 = blockIdx.x * 128;
    const int tx = tid & 15, ty = tid >> 4;
    float acc[8][8];
#pragma unroll
    for (int i=0;i<8;i++)
#pragma unroll
        for (int j=0;j<8;j++) acc[i][j] = 0.f;

    for (int k0 = 0; k0 < K; k0 += 16) {
#pragma unroll
        for (int it = 0; it < 2; it++) {
            int idx = tid + it*256;
            int r  = idx >> 2;
            int c4 = (idx & 3) << 2;
            const float4 v = *reinterpret_cast<const float4*>(A + (size_t)(m0+r)*K + k0 + c4);
            As[c4+0][r]=v.x; As[c4+1][r]=v.y; As[c4+2][r]=v.z; As[c4+3][r]=v.w;
        }
#pragma unroll
        for (int it = 0; it < 2; it++) {
            int idx = tid + it*256;
            int r  = idx >> 5;
            int c4 = (idx & 31) << 2;
            *reinterpret_cast<float4*>(&Bs[r][c4]) =
                *reinterpret_cast<const float4*>(Bm + (size_t)(k0+r)*N + n0 + c4);
        }
        __syncthreads();
#pragma unroll
        for (int k = 0; k < 16; k++) {
            float a[8], b[8];
            *reinterpret_cast<float4*>(&a[0]) = *reinterpret_cast<float4*>(&As[k][ty*4]);
            *reinterpret_cast<float4*>(&a[4]) = *reinterpret_cast<float4*>(&As[k][ty*4+64]);
            *reinterpret_cast<float4*>(&b[0]) = *reinterpret_cast<float4*>(&Bs[k][tx*4]);
            *reinterpret_cast<float4*>(&b[4]) = *reinterpret_cast<float4*>(&Bs[k][tx*4+64]);
#pragma unroll
            for (int i=0;i<8;i++)
#pragma unroll
                for (int j=0;j<8;j++) acc[i][j] += a[i]*b[j];
        }
        __syncthreads();
    }
#pragma unroll
    for (int i=0;i<8;i++){
        int m = m0 + ty*4 + (i&3) + ((i>>2)<<6);
#pragma unroll
        for (int jg=0;jg<2;jg++){
            int n = n0 + tx*4 + jg*64;
            float4 v;
            v.x = acc[i][jg*4+0]; v.y = acc[i][jg*4+1];
            v.z = acc[i][jg*4+2]; v.w = acc[i][jg*4+3];
            if (bias){
                const float4 bv = *reinterpret_cast<const float4*>(bias + n);
                v.x += bv.x; v.y += bv.y; v.z += bv.z; v.w += bv.w;
            }
            *reinterpret_cast<float4*>(C + (size_t)m*N + n) = v;
        }
    }
}

// ---------------- pred GEMM with split-bf16 packed output ---------------------
__device__ __forceinline__ uint32_t pack2bf(__nv_bfloat16 a, __nv_bfloat16 b){
    __nv_bfloat162 t; t.x = a; t.y = b;
    return *reinterpret_cast<uint32_t*>(&t);
}

__global__ void __launch_bounds__(256) gemm_pred_pack_kernel(
    const float* __restrict__ A, const float* __restrict__ Bm,
    const float* __restrict__ bias, __nv_bfloat16* __restrict__ P,
    int M, int N, int K)
{
    __shared__ float As[16][128];
    __shared__ float Bs[16][128];
    const int tid = threadIdx.x;
    const int m0 = blockIdx.y * 128, n0 = blockIdx.x * 128;
    const int tx = tid & 15, ty = tid >> 4;
    float acc[8][8];
#pragma unroll
    for (int i=0;i<8;i++)
#pragma unroll
        for (int j=0;j<8;j++) acc[i][j] = 0.f;

    for (int k0 = 0; k0 < K; k0 += 16) {
#pragma unroll
        for (int it = 0; it < 2; it++) {
            int idx = tid + it*256;
            int r  = idx >> 2;
            int c4 = (idx & 3) << 2;
            const float4 v = *reinterpret_cast<const float4*>(A + (size_t)(m0+r)*K + k0 + c4);
            As[c4+0][r]=v.x; As[c4+1][r]=v.y; As[c4+2][r]=v.z; As[c4+3][r]=v.w;
        }
#pragma unroll
        for (int it = 0; it < 2; it++) {
            int idx = tid + it*256;
            int r  = idx >> 5;
            int c4 = (idx & 31) << 2;
            *reinterpret_cast<float4*>(&Bs[r][c4]) =
                *reinterpret_cast<const float4*>(Bm + (size_t)(k0+r)*N + n0 + c4);
        }
        __syncthreads();
#pragma unroll
        for (int k = 0; k < 16; k++) {
            float a[8], b[8];
            *reinterpret_cast<float4*>(&a[0]) = *reinterpret_cast<float4*>(&As[k][ty*4]);
            *reinterpret_cast<float4*>(&a[4]) = *reinterpret_cast<float4*>(&As[k][ty*4+64]);
            *reinterpret_cast<float4*>(&b[0]) = *reinterpret_cast<float4*>(&Bs[k][tx*4]);
            *reinterpret_cast<float4*>(&b[4]) = *reinterpret_cast<float4*>(&Bs[k][tx*4+64]);
#pragma unroll
            for (int i=0;i<8;i++)
#pragma unroll
                for (int j=0;j<8;j++) acc[i][j] += a[i]*b[j];
        }
        __syncthreads();
    }
    const int kk = n0 >> 7;   // one k per N-block (N tile = 128)
#pragma unroll
    for (int i=0;i<8;i++){
        int m = m0 + ty*4 + (i&3) + ((i>>2)<<6);
        __nv_bfloat16* rowp = P + ((size_t)m*NK + kk)*256;
#pragma unroll
        for (int jg=0;jg<2;jg++){
            int p = tx*4 + jg*64;
            float v0 = acc[i][jg*4+0] + bias[n0+p+0];
            float v1 = acc[i][jg*4+1] + bias[n0+p+1];
            float v2 = acc[i][jg*4+2] + bias[n0+p+2];
            float v3 = acc[i][jg*4+3] + bias[n0+p+3];
            __nv_bfloat16 h0=__float2bfloat16(v0), h1=__float2bfloat16(v1);
            __nv_bfloat16 h2=__float2bfloat16(v2), h3=__float2bfloat16(v3);
            uint2 hv, lv;
            hv.x = pack2bf(h0,h1); hv.y = pack2bf(h2,h3);
            lv.x = pack2bf(__float2bfloat16(v0-__bfloat162float(h0)),
                           __float2bfloat16(v1-__bfloat162float(h1)));
            lv.y = pack2bf(__float2bfloat16(v2-__bfloat162float(h2)),
                           __float2bfloat16(v3-__bfloat162float(h3)));
            *reinterpret_cast<uint2*>(rowp + p)       = hv;
            *reinterpret_cast<uint2*>(rowp + 128 + p) = lv;
        }
    }
}

// ---------------- GRU scan: 16 clusters of 8 CTAs, 4 batches per cluster ------
__device__ __forceinline__ void st_cluster_f32(unsigned laddr, int rank, float v){
    unsigned raddr;
    asm volatile("mapa.shared::cluster.u32 %0, %1, %2;" : "=r"(raddr) : "r"(laddr), "r"(rank));
    asm volatile("st.shared::cluster.f32 [%0], %1;" :: "r"(raddr), "f"(v) : "memory");
}
__device__ __forceinline__ void cluster_sync_all(){
    asm volatile("barrier.cluster.arrive.aligned;" ::: "memory");
    asm volatile("barrier.cluster.wait.aligned;"   ::: "memory");
}

#define GRU_SMEM_FLOATS 28576
#define GRU_SMEM_BYTES  (GRU_SMEM_FLOATS*4)

__global__ void __launch_bounds__(384) __cluster_dims__(8,1,1)
gru_kernel(const float* __restrict__ gi, const float* __restrict__ Wh,
           const float* __restrict__ bhn, float* __restrict__ c_out)
{
    extern __shared__ float sm[];
    float* Whs   = sm;            // [256][96]
    float* h2    = sm + 24576;    // [2][256][4]
    float* part  = sm + 26624;    // [4][96][4]
    float* ghs   = sm + 28160;    // [4][96]
    float* bhn_s = sm + 28544;    // [32]

    const int tid  = threadIdx.x;
    const int rank = blockIdx.x & 7;
    const int b0   = (blockIdx.x >> 3) * 4;
    const int u0   = rank * 32;

    for (int i = tid; i < 256*96; i += 384){
        int u = i / 96, c = i % 96;
        int gcol = (c >> 5)*256 + u0 + (c & 31);
        Whs[i] = Wh[u*768 + gcol];
    }
    for (int i = tid; i < 2048; i += 384) h2[i] = 0.f;
    if (tid < 32) bhn_s[tid] = bhn[u0 + tid];
    __syncthreads();
    cluster_sync_all();

    const int c  = tid % 96;
    const int q  = tid / 96;
    const int b3 = tid >> 5;
    const int ul = tid & 31;

    int cur = 0;
    for (int t = 0; t < NT; t++){
        float gir=0.f, giz=0.f, gin=0.f;
        if (tid < 128){
            const float* gp = gi + ((size_t)(b0+b3)*NT + t)*768;
            gir = gp[u0+ul]; giz = gp[256+u0+ul]; gin = gp[512+u0+ul];
        }
        {
            const float* hb = h2 + cur*1024;
            float a0=0.f,a1=0.f,a2=0.f,a3=0.f;
            const int ub = q*64;
#pragma unroll 8
            for (int uu = 0; uu < 64; uu++){
                int u = ub + uu;
                float w = Whs[u*96 + c];
                float4 h4 = *reinterpret_cast<const float4*>(hb + u*4);
                a0 += w*h4.x; a1 += w*h4.y; a2 += w*h4.z; a3 += w*h4.w;
            }
            float* pp = part + (q*96 + c)*4;
            pp[0]=a0; pp[1]=a1; pp[2]=a2; pp[3]=a3;
        }
        __syncthreads();
        {
            int c2 = tid % 96, b2 = tid / 96;
            float s = part[(0*96+c2)*4+b2] + part[(1*96+c2)*4+b2]
                    + part[(2*96+c2)*4+b2] + part[(3*96+c2)*4+b2];
            ghs[b2*96 + c2] = s;
        }
        __syncthreads();

        int nxt = cur ^ 1;
        if (tid < 128){
            float hr = ghs[b3*96 + ul];
            float hz = ghs[b3*96 + 32 + ul];
            float hn = ghs[b3*96 + 64 + ul];
            float r  = 1.f/(1.f + expf(-(gir + hr)));
            float zz = 1.f/(1.f + expf(-(giz + hz)));
            float n  = tanhf(gin + r*(hn + bhn_s[ul]));
            float hp = h2[cur*1024 + (u0+ul)*4 + b3];
            float hnew = (1.f - zz)*n + zz*hp;
            c_out[((size_t)(b0+b3)*NT + t)*NH + (u0+ul)] = hnew;
            unsigned laddr = smem_u32(h2 + nxt*1024 + (u0+ul)*4 + b3);
#pragma unroll
            for (int r8 = 0; r8 < 8; r8++) st_cluster_f32(laddr, r8, hnew);
        }
        cluster_sync_all();
        cur = nxt;
    }
}

// ---------------- mma.sync streaming-softmax contrastive loss -----------------
// grid (4 t-tiles, 64 b, 12 k), 256 threads (8 warps).
// Warp w owns logits rows m0=16w..m0+15, all 128 cols. Split-bf16 3-term MMA.
// One smem buffer (128 rows x 264 bf16, 528B stride) reused: A staging, then Z per j-tile.
#define LOSS_RS 264
#define LOSS_SMEM_BYTES (128*LOSS_RS*2)

__device__ __forceinline__ void ldmatrix_x4(uint32_t& r0, uint32_t& r1, uint32_t& r2, uint32_t& r3,
                                            uint32_t addr){
    asm volatile("ldmatrix.sync.aligned.m8n8.x4.shared.b16 {%0,%1,%2,%3}, [%4];"
        : "=r"(r0), "=r"(r1), "=r"(r2), "=r"(r3) : "r"(addr));
}
__device__ __forceinline__ void mma16816(float* d, const uint32_t* a, uint32_t b0, uint32_t b1){
    asm volatile("mma.sync.aligned.m16n8k16.row.col.f32.bf16.bf16.f32 "
        "{%0,%1,%2,%3}, {%4,%5,%6,%7}, {%8,%9}, {%0,%1,%2,%3};"
        : "+f"(d[0]), "+f"(d[1]), "+f"(d[2]), "+f"(d[3])
        : "r"(a[0]), "r"(a[1]), "r"(a[2]), "r"(a[3]), "r"(b0), "r"(b1));
}

__global__ void __launch_bounds__(256) loss_mma_kernel(
    const __nv_bfloat16* __restrict__ predp, const __nv_bfloat16* __restrict__ zp,
    float* __restrict__ out)
{
    extern __shared__ __align__(16) char lsm[];
    __nv_bfloat16* S = reinterpret_cast<__nv_bfloat16*>(lsm);
    const uint32_t Sb = smem_u32(lsm);
    __shared__ float wsum[16];

    const int tid  = threadIdx.x;
    const int warp = tid >> 5;
    const int lane = tid & 31;
    const int b    = blockIdx.y;
    const int k    = blockIdx.z + 1;
    const int t0   = blockIdx.x * 128;
    const int Tm   = NT - k;

    // ---- stage A (pred split rows) into S ----
    for (int it = 0; it < 16; it++){
        int idx = tid + it*256;           // 4096 16B units
        int r = idx >> 5, u = idx & 31;
        uint4 v = reinterpret_cast<const uint4*>(
            predp + (((size_t)(b*NT + t0 + r))*NK + (k-1))*256)[u];
        *reinterpret_cast<uint4*>(S + r*LOSS_RS + u*8) = v;
    }
    __syncthreads();

    // ---- load A fragments into registers (warp rows m0..m0+15, K=256) ----
    const int m0 = warp * 16;
    const uint32_t lrow = (lane & 7) + ((lane >> 3) & 1)*8;
    const uint32_t lcol = (lane >> 4)*8;
    uint32_t afr[16][4];
#pragma unroll
    for (int kc = 0; kc < 16; kc++){
        uint32_t addr = Sb + ((m0 + lrow)*LOSS_RS + kc*16 + lcol)*2;
        ldmatrix_x4(afr[kc][0], afr[kc][1], afr[kc][2], afr[kc][3], addr);
    }
    __syncthreads();

    // softmax state: rows r0 = t0+m0+(lane>>2), r1 = r0+8
    const int ra = t0 + m0 + (lane >> 2);
    const bool rv0 = ra < Tm, rv1 = (ra + 8) < Tm;
    float mr[2] = {-1e30f, -1e30f};
    float sr[2] = {0.f, 0.f};
    float tot = 0.f;

    for (int jt = 0; jt < 4; jt++){
        const int j0 = jt * 128;
        // ---- stage Z tile ----
        for (int it = 0; it < 16; it++){
            int idx = tid + it*256;
            int j = idx >> 5, u = idx & 31;
            int jr = k + j0 + j;
            uint4 v = make_uint4(0u,0u,0u,0u);
            if (jr < NT)
                v = reinterpret_cast<const uint4*>(zp + ((size_t)(b*NT) + jr)*256)[u];
            *reinterpret_cast<uint4*>(S + j*LOSS_RS + u*8) = v;
        }
        __syncthreads();

        float acc[16][4];
#pragma unroll
        for (int nf = 0; nf < 16; nf++)
#pragma unroll
            for (int i = 0; i < 4; i++) acc[nf][i] = 0.f;

        // 3 terms: (aoff,boff) in kc-units of 16: (0,0) hi*hi, (0,8) hi*lo, (8,0) lo*hi
#pragma unroll
        for (int term = 0; term < 3; term++){
            const int ao = (term == 2) ? 8 : 0;
            const int bo = (term == 1) ? 8 : 0;
#pragma unroll
            for (int kc = 0; kc < 8; kc++){
                const uint32_t* A = afr[kc + ao];
                const uint32_t bcol = (kc + bo)*16 + lcol;
#pragma unroll
                for (int nf2 = 0; nf2 < 8; nf2++){
                    uint32_t r0,r1,r2,r3;
                    uint32_t addr = Sb + ((nf2*16 + lrow)*LOSS_RS + bcol)*2;
                    ldmatrix_x4(r0, r1, r2, r3, addr);
                    mma16816(acc[nf2*2+0], A, r0, r2);
                    mma16816(acc[nf2*2+1], A, r1, r3);
                }
            }
        }
        __syncthreads();   // ldmatrix done; S can be restaged next iter

        // ---- epilogue: streaming softmax over this 128-col tile ----
        const int cbase = j0 + (lane & 3)*2;
        float tm[2] = {-1e30f, -1e30f};
#pragma unroll
        for (int nf = 0; nf < 16; nf++){
            int c0 = cbase + nf*8;
            bool v0 = c0 < Tm, v1 = (c0+1) < Tm;
            if (v0){ tm[0] = fmaxf(tm[0], acc[nf][0]); tm[1] = fmaxf(tm[1], acc[nf][2]); }
            if (v1){ tm[0] = fmaxf(tm[0], acc[nf][1]); tm[1] = fmaxf(tm[1], acc[nf][3]); }
        }
        tm[0] *= INV_TEMP; tm[1] *= INV_TEMP;
        // quad reduce (row spread over lanes xor 1, 2)
#pragma unroll
        for (int o = 1; o <= 2; o <<= 1){
            tm[0] = fmaxf(tm[0], __shfl_xor_sync(0xFFFFFFFFu, tm[0], o));
            tm[1] = fmaxf(tm[1], __shfl_xor_sync(0xFFFFFFFFu, tm[1], o));
        }
        if (tm[0] > -1e29f){
#pragma unroll
            for (int rr = 0; rr < 2; rr++){
                float nm = fmaxf(mr[rr], tm[rr]);
                sr[rr] *= __expf(mr[rr] - nm);
                mr[rr] = nm;
            }
            float ls0 = 0.f, ls1 = 0.f, lt0 = 0.f, lt1 = 0.f;
#pragma unroll
            for (int nf = 0; nf < 16; nf++){
                int c0 = cbase + nf*8;
#pragma unroll
                for (int h = 0; h < 2; h++){
                    if (c0 + h < Tm){
                        float x0 = acc[nf][h]   * INV_TEMP;
                        float x1 = acc[nf][2+h] * INV_TEMP;
                        ls0 += __expf(x0 - mr[0]);
                        ls1 += __expf(x1 - mr[1]);
                        lt0 += x0; lt1 += x1;
                    }
                }
            }
            sr[0] += ls0; sr[1] += ls1;
            if (rv0) tot += lt0;
            if (rv1) tot += lt1;
        }
    }

    // ---- finalize: quad-sum s, lse per row, block reduce ----
#pragma unroll
    for (int o = 1; o <= 2; o <<= 1){
        sr[0] += __shfl_xor_sync(0xFFFFFFFFu, sr[0], o);
        sr[1] += __shfl_xor_sync(0xFFFFFFFFu, sr[1], o);
    }
    float lse = 0.f;
    if ((lane & 3) == 0){
        if (rv0) lse += mr[0] + __logf(sr[0]);
        if (rv1) lse += mr[1] + __logf(sr[1]);
    }
#pragma unroll
    for (int o = 16; o; o >>= 1){
        lse += __shfl_xor_sync(0xFFFFFFFFu, lse, o);
        tot += __shfl_xor_sync(0xFFFFFFFFu, tot, o);
    }
    if (lane == 0){ wsum[warp] = lse; wsum[8+warp] = tot; }
    __syncthreads();
    if (tid == 0){
        float L = 0.f, T = 0.f;
#pragma unroll
        for (int w = 0; w < 8; w++){ L += wsum[w]; T += wsum[8+w]; }
        float inv = 1.0f / ((float)NB * (float)Tm * (float)NK);
        atomicAdd(out, L*inv - T*(inv/(float)Tm));
    }
}

// ---------------- launch ------------------------------------------------------
extern "C" void kernel_launch(void* const* d_in, const int* in_sizes, int n_in,
                              void* d_out, int out_size)
{
    const float* x_seq  = (const float*)d_in[0];
    const float* W_enc  = (const float*)d_in[1];
    const float* b_enc  = (const float*)d_in[2];
    const float* W_proj = (const float*)d_in[3];
    const float* b_proj = (const float*)d_in[4];
    const float* Wi     = (const float*)d_in[5];
    const float* bi     = (const float*)d_in[6];
    const float* Wh     = (const float*)d_in[7];
    const float* bhn    = (const float*)d_in[8];
    const float* Wp     = (const float*)d_in[9];
    const float* bp     = (const float*)d_in[10];
    float* out = (float*)d_out;

    float *Wf, *bz, *Wpc, *zbuf, *gibuf, *cbuf;
    __nv_bfloat16 *predp, *zpb;
    cudaGetSymbolAddress((void**)&Wf,    g_Wf);
    cudaGetSymbolAddress((void**)&bz,    g_bz);
    cudaGetSymbolAddress((void**)&Wpc,   g_Wpc);
    cudaGetSymbolAddress((void**)&zbuf,  g_z);
    cudaGetSymbolAddress((void**)&gibuf, g_gi);
    cudaGetSymbolAddress((void**)&cbuf,  g_c);
    cudaGetSymbolAddress((void**)&predp, g_predp);
    cudaGetSymbolAddress((void**)&zpb,   g_zp);

    cudaFuncSetAttribute(gru_kernel,      cudaFuncAttributeMaxDynamicSharedMemorySize, GRU_SMEM_BYTES);
    cudaFuncSetAttribute(loss_mma_kernel, cudaFuncAttributeMaxDynamicSharedMemorySize, LOSS_SMEM_BYTES);

    zero_loss_kernel<<<1, 32>>>(out);
    bz_kernel<<<1, 128>>>(b_enc, W_proj, b_proj, bz);

    // Wf = W_enc @ W_proj   (256x128x256)
    gemm_bias_kernel<<<dim3(1,2), 256>>>(W_enc, W_proj, nullptr, Wf, 256, 128, 256);
    // z = x @ Wf + bz       (32768x128x256)
    gemm_bias_kernel<<<dim3(1,256), 256>>>(x_seq, Wf, bz, zbuf, BT, NP, NF);
    // zp split pack
    zpack_kernel<<<(BT*NP+255)/256, 256>>>(zbuf, zpb);
    // gi = z @ Wi + bi      (32768x768x128)
    gemm_bias_kernel<<<dim3(6,256), 256>>>(zbuf, Wi, bi, gibuf, BT, 3*NH, NP);
    // repack Wp
    repack_wp_kernel<<<768, 512>>>(Wp, Wpc);
    // GRU scan (persistent, clustered)
    gru_kernel<<<128, 384, GRU_SMEM_BYTES>>>(gibuf, Wh, bhn, cbuf);
    // pred = c @ Wpc + bp -> split-bf16 packed  (32768x1536x256)
    gemm_pred_pack_kernel<<<dim3(12,256), 256>>>(cbuf, Wpc, bp, predp, BT, NK*NP, NH);
    // mma.sync streaming-softmax loss
    loss_mma_kernel<<<dim3(4,64,12), 256, LOSS_SMEM_BYTES>>>(predp, zpb, out);
}

// round 6
// speedup vs baseline: 1.3070x; 1.1121x over previous
#include <cuda_runtime.h>
#include <cuda_bf16.h>
#include <cstdint>
#include <math.h>

// Problem constants
#define NB 64
#define NT 512
#define NF 256
#define NP 128
#define NH 256
#define NK 12
#define INV_TEMP 10.0f
#define BT (NB*NT)   // 32768

// ---------------- device scratch (no allocations allowed) ---------------------
__device__ float g_Wf[NF*NP];                       // fused encoder weight 256x128
__device__ float g_bz[NP];                          // fused encoder bias
__device__ float g_z[(size_t)BT*NP];                // z_seq   (b,t,128)
__device__ float g_gi[(size_t)BT*3*NH];             // gi      (b,t,768)
__device__ float g_c[(size_t)BT*NH];                // c_seq   (b,t,256)
__device__ __align__(16) __nv_bfloat16 g_predp[(size_t)BT*NK*256]; // pred split [hi|lo]
__device__ __align__(16) __nv_bfloat16 g_zp[(size_t)BT*256];       // z split [hi|lo]
__device__ __align__(16) __nv_bfloat16 g_cp[(size_t)BT*512];       // c split per-half [hi|lo]
__device__ __align__(16) __nv_bfloat16 g_wps[(size_t)2*1536*256];  // Wp split n-major

// ---------------- helpers -----------------------------------------------------
__device__ __forceinline__ unsigned smem_u32(const void* p){
    unsigned r;
    asm("{ .reg .u64 t; cvta.to.shared.u64 t, %1; cvt.u32.u64 %0, t; }" : "=r"(r) : "l"(p));
    return r;
}

__global__ void zero_loss_kernel(float* p){ if (threadIdx.x==0) *p = 0.f; }

__global__ void bz_kernel(const float* __restrict__ b_enc, const float* __restrict__ W_proj,
                          const float* __restrict__ b_proj, float* __restrict__ bz){
    int n = threadIdx.x;            // 128
    float s = b_proj[n];
    for (int e = 0; e < NF; e++) s += b_enc[e] * W_proj[e*NP + n];
    bz[n] = s;
}

// Wp (12,256,128) -> wps[khalf][n=k*128+p][kr(256): hi(0..127)|lo(128..255)]
__global__ void repack_wp_kernel(const float* __restrict__ Wp, __nv_bfloat16* __restrict__ wps){
    int idx = blockIdx.x*blockDim.x + threadIdx.x;
    if (idx >= NK*NH*NP) return;
    int p = idx & 127;
    int h = (idx >> 7) & 255;
    int k = idx >> 15;
    float v = Wp[idx];
    __nv_bfloat16 hi = __float2bfloat16(v);
    __nv_bfloat16 lo = __float2bfloat16(v - __bfloat162float(hi));
    int n = k*128 + p;
    int khalf = h >> 7, kr = h & 127;
    size_t base = ((size_t)khalf*1536 + n)*256;
    wps[base + kr]       = hi;
    wps[base + 128 + kr] = lo;
}

// z fp32 -> split bf16 [hi(128)|lo(128)]
__global__ void zpack_kernel(const float* __restrict__ z, __nv_bfloat16* __restrict__ zp){
    int idx = blockIdx.x*blockDim.x + threadIdx.x;
    if (idx >= BT*NP) return;
    int row = idx >> 7, c = idx & 127;
    float v = z[idx];
    __nv_bfloat16 h = __float2bfloat16(v);
    zp[(size_t)row*256 + c]       = h;
    zp[(size_t)row*256 + 128 + c] = __float2bfloat16(v - __bfloat162float(h));
}

// c fp32 (BT x 256) -> cp rows [h0hi(128), h0lo(128), h1hi(128), h1lo(128)]
__global__ void cpack_kernel(const float* __restrict__ c, __nv_bfloat16* __restrict__ cp){
    int idx = blockIdx.x*blockDim.x + threadIdx.x;
    if (idx >= BT*NH) return;
    int row = idx >> 8, ch = idx & 255;
    int half = ch >> 7, w = ch & 127;
    float v = c[idx];
    __nv_bfloat16 h = __float2bfloat16(v);
    size_t base = (size_t)row*512 + half*256;
    cp[base + w]       = h;
    cp[base + 128 + w] = __float2bfloat16(v - __bfloat162float(h));
}

// ---------------- generic tiled GEMM: C = A(MxK) @ B(KxN) + bias --------------
__global__ void __launch_bounds__(256) gemm_bias_kernel(
    const float* __restrict__ A, const float* __restrict__ Bm,
    const float* __restrict__ bias, float* __restrict__ C,
    int M, int N, int K)
{
    __shared__ float As[16][128];
    __shared__ float Bs[16][128];
    const int tid = threadIdx.x;
    const int m0 = blockIdx.y * 128, n0 = blockIdx.x * 128;
    const int tx = tid & 15, ty = tid >> 4;
    float acc[8][8];
#pragma unroll
    for (int i=0;i<8;i++)
#pragma unroll
        for (int j=0;j<8;j++) acc[i][j] = 0.f;

    for (int k0 = 0; k0 < K; k0 += 16) {
#pragma unroll
        for (int it = 0; it < 2; it++) {
            int idx = tid + it*256;
            int r  = idx >> 2;
            int c4 = (idx & 3) << 2;
            const float4 v = *reinterpret_cast<const float4*>(A + (size_t)(m0+r)*K + k0 + c4);
            As[c4+0][r]=v.x; As[c4+1][r]=v.y; As[c4+2][r]=v.z; As[c4+3][r]=v.w;
        }
#pragma unroll
        for (int it = 0; it < 2; it++) {
            int idx = tid + it*256;
            int r  = idx >> 5;
            int c4 = (idx & 31) << 2;
            *reinterpret_cast<float4*>(&Bs[r][c4]) =
                *reinterpret_cast<const float4*>(Bm + (size_t)(k0+r)*N + n0 + c4);
        }
        __syncthreads();
#pragma unroll
        for (int k = 0; k < 16; k++) {
            float a[8], b[8];
            *reinterpret_cast<float4*>(&a[0]) = *reinterpret_cast<float4*>(&As[k][ty*4]);
            *reinterpret_cast<float4*>(&a[4]) = *reinterpret_cast<float4*>(&As[k][ty*4+64]);
            *reinterpret_cast<float4*>(&b[0]) = *reinterpret_cast<float4*>(&Bs[k][tx*4]);
            *reinterpret_cast<float4*>(&b[4]) = *reinterpret_cast<float4*>(&Bs[k][tx*4+64]);
#pragma unroll
            for (int i=0;i<8;i++)
#pragma unroll
                for (int j=0;j<8;j++) acc[i][j] += a[i]*b[j];
        }
        __syncthreads();
    }
#pragma unroll
    for (int i=0;i<8;i++){
        int m = m0 + ty*4 + (i&3) + ((i>>2)<<6);
#pragma unroll
        for (int jg=0;jg<2;jg++){
            int n = n0 + tx*4 + jg*64;
            float4 v;
            v.x = acc[i][jg*4+0]; v.y = acc[i][jg*4+1];
            v.z = acc[i][jg*4+2]; v.w = acc[i][jg*4+3];
            if (bias){
                const float4 bv = *reinterpret_cast<const float4*>(bias + n);
                v.x += bv.x; v.y += bv.y; v.z += bv.z; v.w += bv.w;
            }
            *reinterpret_cast<float4*>(C + (size_t)m*N + n) = v;
        }
    }
}

// ---------------- mma primitives ----------------------------------------------
__device__ __forceinline__ void ldmatrix_x4(uint32_t& r0, uint32_t& r1, uint32_t& r2, uint32_t& r3,
                                            uint32_t addr){
    asm volatile("ldmatrix.sync.aligned.m8n8.x4.shared.b16 {%0,%1,%2,%3}, [%4];"
        : "=r"(r0), "=r"(r1), "=r"(r2), "=r"(r3) : "r"(addr));
}
__device__ __forceinline__ void mma16816(float* d, const uint32_t* a, uint32_t b0, uint32_t b1){
    asm volatile("mma.sync.aligned.m16n8k16.row.col.f32.bf16.bf16.f32 "
        "{%0,%1,%2,%3}, {%4,%5,%6,%7}, {%8,%9}, {%0,%1,%2,%3};"
        : "+f"(d[0]), "+f"(d[1]), "+f"(d[2]), "+f"(d[3])
        : "r"(a[0]), "r"(a[1]), "r"(a[2]), "r"(a[3]), "r"(b0), "r"(b1));
}
__device__ __forceinline__ uint32_t pack2bf(__nv_bfloat16 a, __nv_bfloat16 b){
    __nv_bfloat162 t; t.x = a; t.y = b;
    return *reinterpret_cast<uint32_t*>(&t);
}

// ---------------- pred GEMM via mma.sync (3-term split bf16) -------------------
// grid (12 n-tiles, 256 m-tiles), 256 threads. pred = c @ Wp[k] + bp[k],
// output split-bf16 packed [hi(128)|lo(128)] per (m,k) row.
#define PRS 264
#define PRED_SMEM_BYTES (2*128*PRS*2)

__global__ void __launch_bounds__(256) pred_mma_kernel(
    const __nv_bfloat16* __restrict__ cp, const __nv_bfloat16* __restrict__ wps,
    const float* __restrict__ bp, __nv_bfloat16* __restrict__ predp)
{
    extern __shared__ __align__(16) char psm[];
    __nv_bfloat16* SA = reinterpret_cast<__nv_bfloat16*>(psm);
    __nv_bfloat16* SB = SA + 128*PRS;
    const uint32_t SAb = smem_u32(SA);
    const uint32_t SBb = smem_u32(SB);

    const int tid  = threadIdx.x;
    const int warp = tid >> 5;
    const int lane = tid & 31;
    const int kk   = blockIdx.x;          // head index, n0 = kk*128
    const int m0   = blockIdx.y * 128;
    const int n0   = kk * 128;

    const uint32_t lrow = (lane & 7) + ((lane >> 3) & 1)*8;
    const uint32_t lcol = (lane >> 4)*8;
    const int mw = warp * 16;

    float acc[16][4];
#pragma unroll
    for (int nf = 0; nf < 16; nf++)
#pragma unroll
        for (int i = 0; i < 4; i++) acc[nf][i] = 0.f;

    for (int khalf = 0; khalf < 2; khalf++){
        // stage A: 128 rows x 256 bf16 (c split, this half)
        for (int it = 0; it < 16; it++){
            int idx = tid + it*256;
            int r = idx >> 5, u = idx & 31;
            uint4 v = *reinterpret_cast<const uint4*>(
                cp + (size_t)(m0 + r)*512 + khalf*256 + u*8);
            *reinterpret_cast<uint4*>(SA + r*PRS + u*8) = v;
        }
        // stage B: 128 n-rows x 256 bf16 (Wp split, n-major)
        for (int it = 0; it < 16; it++){
            int idx = tid + it*256;
            int n = idx >> 5, u = idx & 31;
            uint4 v = *reinterpret_cast<const uint4*>(
                wps + ((size_t)khalf*1536 + n0 + n)*256 + u*8);
            *reinterpret_cast<uint4*>(SB + n*PRS + u*8) = v;
        }
        __syncthreads();

        // A fragments for this half
        uint32_t afr[16][4];
#pragma unroll
        for (int kc = 0; kc < 16; kc++){
            uint32_t addr = SAb + ((mw + lrow)*PRS + kc*16 + lcol)*2;
            ldmatrix_x4(afr[kc][0], afr[kc][1], afr[kc][2], afr[kc][3], addr);
        }

#pragma unroll
        for (int kc = 0; kc < 16; kc++){
#pragma unroll
            for (int nf2 = 0; nf2 < 8; nf2++){
                uint32_t r0,r1,r2,r3;
                uint32_t addr = SBb + ((nf2*16 + lrow)*PRS + kc*16 + lcol)*2;
                ldmatrix_x4(r0, r1, r2, r3, addr);
                if (kc < 8){
                    mma16816(acc[nf2*2+0], afr[kc],   r0, r2);
                    mma16816(acc[nf2*2+1], afr[kc],   r1, r3);
                    mma16816(acc[nf2*2+0], afr[kc+8], r0, r2);
                    mma16816(acc[nf2*2+1], afr[kc+8], r1, r3);
                } else {
                    mma16816(acc[nf2*2+0], afr[kc-8], r0, r2);
                    mma16816(acc[nf2*2+1], afr[kc-8], r1, r3);
                }
            }
        }
        __syncthreads();
    }

    // epilogue: bias + split-bf16 packed store
    const int r0g = m0 + mw + (lane >> 2);
    __nv_bfloat16* rp0 = predp + ((size_t)r0g*NK + kk)*256;
    __nv_bfloat16* rp1 = predp + ((size_t)(r0g+8)*NK + kk)*256;
#pragma unroll
    for (int nf = 0; nf < 16; nf++){
        int c0 = nf*8 + (lane & 3)*2;
        float b0 = bp[kk*128 + c0], b1 = bp[kk*128 + c0 + 1];
#pragma unroll
        for (int rr = 0; rr < 2; rr++){
            float v0 = acc[nf][rr*2+0] + b0;
            float v1 = acc[nf][rr*2+1] + b1;
            __nv_bfloat16 h0 = __float2bfloat16(v0);
            __nv_bfloat16 h1 = __float2bfloat16(v1);
            uint32_t hv = pack2bf(h0, h1);
            uint32_t lv = pack2bf(__float2bfloat16(v0 - __bfloat162float(h0)),
                                  __float2bfloat16(v1 - __bfloat162float(h1)));
            __nv_bfloat16* rp = rr ? rp1 : rp0;
            *reinterpret_cast<uint32_t*>(rp + c0)       = hv;
            *reinterpret_cast<uint32_t*>(rp + 128 + c0) = lv;
        }
    }
}

// ---------------- GRU scan: 16 clusters of 8 CTAs, 4 batches per cluster ------
__device__ __forceinline__ void st_cluster_f32(unsigned laddr, int rank, float v){
    unsigned raddr;
    asm volatile("mapa.shared::cluster.u32 %0, %1, %2;" : "=r"(raddr) : "r"(laddr), "r"(rank));
    asm volatile("st.shared::cluster.f32 [%0], %1;" :: "r"(raddr), "f"(v) : "memory");
}
__device__ __forceinline__ void cluster_sync_all(){
    asm volatile("barrier.cluster.arrive.aligned;" ::: "memory");
    asm volatile("barrier.cluster.wait.aligned;"   ::: "memory");
}

#define GRU_SMEM_FLOATS 28576
#define GRU_SMEM_BYTES  (GRU_SMEM_FLOATS*4)

__global__ void __launch_bounds__(384) __cluster_dims__(8,1,1)
gru_kernel(const float* __restrict__ gi, const float* __restrict__ Wh,
           const float* __restrict__ bhn, float* __restrict__ c_out)
{
    extern __shared__ float sm[];
    float* Whs   = sm;            // [256][96]
    float* h2    = sm + 24576;    // [2][256][4]
    float* part  = sm + 26624;    // [4][96][4]
    float* ghs   = sm + 28160;    // [4][96]
    float* bhn_s = sm + 28544;    // [32]

    const int tid  = threadIdx.x;
    const int rank = blockIdx.x & 7;
    const int b0   = (blockIdx.x >> 3) * 4;
    const int u0   = rank * 32;

    for (int i = tid; i < 256*96; i += 384){
        int u = i / 96, c = i % 96;
        int gcol = (c >> 5)*256 + u0 + (c & 31);
        Whs[i] = Wh[u*768 + gcol];
    }
    for (int i = tid; i < 2048; i += 384) h2[i] = 0.f;
    if (tid < 32) bhn_s[tid] = bhn[u0 + tid];
    __syncthreads();
    cluster_sync_all();

    const int c  = tid % 96;
    const int q  = tid / 96;
    const int b3 = tid >> 5;
    const int ul = tid & 31;

    int cur = 0;
    for (int t = 0; t < NT; t++){
        float gir=0.f, giz=0.f, gin=0.f;
        if (tid < 128){
            const float* gp = gi + ((size_t)(b0+b3)*NT + t)*768;
            gir = gp[u0+ul]; giz = gp[256+u0+ul]; gin = gp[512+u0+ul];
        }
        {
            const float* hb = h2 + cur*1024;
            float a0=0.f,a1=0.f,a2=0.f,a3=0.f;
            const int ub = q*64;
#pragma unroll 8
            for (int uu = 0; uu < 64; uu++){
                int u = ub + uu;
                float w = Whs[u*96 + c];
                float4 h4 = *reinterpret_cast<const float4*>(hb + u*4);
                a0 += w*h4.x; a1 += w*h4.y; a2 += w*h4.z; a3 += w*h4.w;
            }
            float* pp = part + (q*96 + c)*4;
            pp[0]=a0; pp[1]=a1; pp[2]=a2; pp[3]=a3;
        }
        __syncthreads();
        {
            int c2 = tid % 96, b2 = tid / 96;
            float s = part[(0*96+c2)*4+b2] + part[(1*96+c2)*4+b2]
                    + part[(2*96+c2)*4+b2] + part[(3*96+c2)*4+b2];
            ghs[b2*96 + c2] = s;
        }
        __syncthreads();

        int nxt = cur ^ 1;
        if (tid < 128){
            float hr = ghs[b3*96 + ul];
            float hz = ghs[b3*96 + 32 + ul];
            float hn = ghs[b3*96 + 64 + ul];
            float r  = 1.f/(1.f + expf(-(gir + hr)));
            float zz = 1.f/(1.f + expf(-(giz + hz)));
            float n  = tanhf(gin + r*(hn + bhn_s[ul]));
            float hp = h2[cur*1024 + (u0+ul)*4 + b3];
            float hnew = (1.f - zz)*n + zz*hp;
            c_out[((size_t)(b0+b3)*NT + t)*NH + (u0+ul)] = hnew;
            unsigned laddr = smem_u32(h2 + nxt*1024 + (u0+ul)*4 + b3);
#pragma unroll
            for (int r8 = 0; r8 < 8; r8++) st_cluster_f32(laddr, r8, hnew);
        }
        cluster_sync_all();
        cur = nxt;
    }
}

// ---------------- mma.sync streaming-softmax contrastive loss -----------------
#define LOSS_RS 264
#define LOSS_SMEM_BYTES (128*LOSS_RS*2)

__global__ void __launch_bounds__(256) loss_mma_kernel(
    const __nv_bfloat16* __restrict__ predp, const __nv_bfloat16* __restrict__ zp,
    float* __restrict__ out)
{
    extern __shared__ __align__(16) char lsm[];
    __nv_bfloat16* S = reinterpret_cast<__nv_bfloat16*>(lsm);
    const uint32_t Sb = smem_u32(lsm);
    __shared__ float wsum[16];

    const int tid  = threadIdx.x;
    const int warp = tid >> 5;
    const int lane = tid & 31;
    const int b    = blockIdx.y;
    const int k    = blockIdx.z + 1;
    const int t0   = blockIdx.x * 128;
    const int Tm   = NT - k;

    // ---- stage A (pred split rows) into S ----
    for (int it = 0; it < 16; it++){
        int idx = tid + it*256;
        int r = idx >> 5, u = idx & 31;
        uint4 v = reinterpret_cast<const uint4*>(
            predp + (((size_t)(b*NT + t0 + r))*NK + (k-1))*256)[u];
        *reinterpret_cast<uint4*>(S + r*LOSS_RS + u*8) = v;
    }
    __syncthreads();

    const int m0 = warp * 16;
    const uint32_t lrow = (lane & 7) + ((lane >> 3) & 1)*8;
    const uint32_t lcol = (lane >> 4)*8;
    uint32_t afr[16][4];
#pragma unroll
    for (int kc = 0; kc < 16; kc++){
        uint32_t addr = Sb + ((m0 + lrow)*LOSS_RS + kc*16 + lcol)*2;
        ldmatrix_x4(afr[kc][0], afr[kc][1], afr[kc][2], afr[kc][3], addr);
    }
    __syncthreads();

    const int ra = t0 + m0 + (lane >> 2);
    const bool rv0 = ra < Tm, rv1 = (ra + 8) < Tm;
    float mr[2] = {-1e30f, -1e30f};
    float sr[2] = {0.f, 0.f};
    float tot = 0.f;

    for (int jt = 0; jt < 4; jt++){
        const int j0 = jt * 128;
        // ---- stage Z tile ----
        for (int it = 0; it < 16; it++){
            int idx = tid + it*256;
            int j = idx >> 5, u = idx & 31;
            int jr = k + j0 + j;
            uint4 v = make_uint4(0u,0u,0u,0u);
            if (jr < NT)
                v = reinterpret_cast<const uint4*>(zp + ((size_t)(b*NT) + jr)*256)[u];
            *reinterpret_cast<uint4*>(S + j*LOSS_RS + u*8) = v;
        }
        __syncthreads();

        float acc[16][4];
#pragma unroll
        for (int nf = 0; nf < 16; nf++)
#pragma unroll
            for (int i = 0; i < 4; i++) acc[nf][i] = 0.f;

        // B-frag reuse: kc<8 (Zhi) pairs with Phi (afr[kc]) and Plo (afr[kc+8]);
        // kc>=8 (Zlo) pairs with Phi (afr[kc-8]) only.
#pragma unroll
        for (int kc = 0; kc < 16; kc++){
#pragma unroll
            for (int nf2 = 0; nf2 < 8; nf2++){
                uint32_t r0,r1,r2,r3;
                uint32_t addr = Sb + ((nf2*16 + lrow)*LOSS_RS + kc*16 + lcol)*2;
                ldmatrix_x4(r0, r1, r2, r3, addr);
                if (kc < 8){
                    mma16816(acc[nf2*2+0], afr[kc],   r0, r2);
                    mma16816(acc[nf2*2+1], afr[kc],   r1, r3);
                    mma16816(acc[nf2*2+0], afr[kc+8], r0, r2);
                    mma16816(acc[nf2*2+1], afr[kc+8], r1, r3);
                } else {
                    mma16816(acc[nf2*2+0], afr[kc-8], r0, r2);
                    mma16816(acc[nf2*2+1], afr[kc-8], r1, r3);
                }
            }
        }
        __syncthreads();   // ldmatrix done; S can be restaged next iter

        // ---- epilogue: streaming softmax over this 128-col tile ----
        if (j0 + 128 <= Tm){
            // fast path: all columns valid
            float tm[2] = {-1e30f, -1e30f};
#pragma unroll
            for (int nf = 0; nf < 16; nf++){
                tm[0] = fmaxf(tm[0], fmaxf(acc[nf][0], acc[nf][1]));
                tm[1] = fmaxf(tm[1], fmaxf(acc[nf][2], acc[nf][3]));
            }
            tm[0] *= INV_TEMP; tm[1] *= INV_TEMP;
#pragma unroll
            for (int o = 1; o <= 2; o <<= 1){
                tm[0] = fmaxf(tm[0], __shfl_xor_sync(0xFFFFFFFFu, tm[0], o));
                tm[1] = fmaxf(tm[1], __shfl_xor_sync(0xFFFFFFFFu, tm[1], o));
            }
#pragma unroll
            for (int rr = 0; rr < 2; rr++){
                float nm = fmaxf(mr[rr], tm[rr]);
                sr[rr] *= __expf(mr[rr] - nm);
                mr[rr] = nm;
            }
            float ls0 = 0.f, ls1 = 0.f, lt0 = 0.f, lt1 = 0.f;
#pragma unroll
            for (int nf = 0; nf < 16; nf++){
                float x0 = acc[nf][0]*INV_TEMP, x1 = acc[nf][1]*INV_TEMP;
                float x2 = acc[nf][2]*INV_TEMP, x3 = acc[nf][3]*INV_TEMP;
                ls0 += __expf(x0 - mr[0]) + __expf(x1 - mr[0]);
                ls1 += __expf(x2 - mr[1]) + __expf(x3 - mr[1]);
                lt0 += x0 + x1;
                lt1 += x2 + x3;
            }
            sr[0] += ls0; sr[1] += ls1;
            if (rv0) tot += lt0;
            if (rv1) tot += lt1;
        } else {
            const int cbase = j0 + (lane & 3)*2;
            float tm[2] = {-1e30f, -1e30f};
#pragma unroll
            for (int nf = 0; nf < 16; nf++){
                int c0 = cbase + nf*8;
                bool v0 = c0 < Tm, v1 = (c0+1) < Tm;
                if (v0){ tm[0] = fmaxf(tm[0], acc[nf][0]); tm[1] = fmaxf(tm[1], acc[nf][2]); }
                if (v1){ tm[0] = fmaxf(tm[0], acc[nf][1]); tm[1] = fmaxf(tm[1], acc[nf][3]); }
            }
            tm[0] *= INV_TEMP; tm[1] *= INV_TEMP;
#pragma unroll
            for (int o = 1; o <= 2; o <<= 1){
                tm[0] = fmaxf(tm[0], __shfl_xor_sync(0xFFFFFFFFu, tm[0], o));
                tm[1] = fmaxf(tm[1], __shfl_xor_sync(0xFFFFFFFFu, tm[1], o));
            }
            if (tm[0] > -1e29f){
#pragma unroll
                for (int rr = 0; rr < 2; rr++){
                    float nm = fmaxf(mr[rr], tm[rr]);
                    sr[rr] *= __expf(mr[rr] - nm);
                    mr[rr] = nm;
                }
                float ls0 = 0.f, ls1 = 0.f, lt0 = 0.f, lt1 = 0.f;
#pragma unroll
                for (int nf = 0; nf < 16; nf++){
                    int c0 = cbase + nf*8;
#pragma unroll
                    for (int h = 0; h < 2; h++){
                        if (c0 + h < Tm){
                            float x0 = acc[nf][h]   * INV_TEMP;
                            float x1 = acc[nf][2+h] * INV_TEMP;
                            ls0 += __expf(x0 - mr[0]);
                            ls1 += __expf(x1 - mr[1]);
                            lt0 += x0; lt1 += x1;
                        }
                    }
                }
                sr[0] += ls0; sr[1] += ls1;
                if (rv0) tot += lt0;
                if (rv1) tot += lt1;
            }
        }
    }

    // ---- finalize ----
#pragma unroll
    for (int o = 1; o <= 2; o <<= 1){
        sr[0] += __shfl_xor_sync(0xFFFFFFFFu, sr[0], o);
        sr[1] += __shfl_xor_sync(0xFFFFFFFFu, sr[1], o);
    }
    float lse = 0.f;
    if ((lane & 3) == 0){
        if (rv0) lse += mr[0] + __logf(sr[0]);
        if (rv1) lse += mr[1] + __logf(sr[1]);
    }
#pragma unroll
    for (int o = 16; o; o >>= 1){
        lse += __shfl_xor_sync(0xFFFFFFFFu, lse, o);
        tot += __shfl_xor_sync(0xFFFFFFFFu, tot, o);
    }
    if (lane == 0){ wsum[warp] = lse; wsum[8+warp] = tot; }
    __syncthreads();
    if (tid == 0){
        float L = 0.f, T = 0.f;
#pragma unroll
        for (int w = 0; w < 8; w++){ L += wsum[w]; T += wsum[8+w]; }
        float inv = 1.0f / ((float)NB * (float)Tm * (float)NK);
        atomicAdd(out, L*inv - T*(inv/(float)Tm));
    }
}

// ---------------- launch ------------------------------------------------------
extern "C" void kernel_launch(void* const* d_in, const int* in_sizes, int n_in,
                              void* d_out, int out_size)
{
    const float* x_seq  = (const float*)d_in[0];
    const float* W_enc  = (const float*)d_in[1];
    const float* b_enc  = (const float*)d_in[2];
    const float* W_proj = (const float*)d_in[3];
    const float* b_proj = (const float*)d_in[4];
    const float* Wi     = (const float*)d_in[5];
    const float* bi     = (const float*)d_in[6];
    const float* Wh     = (const float*)d_in[7];
    const float* bhn    = (const float*)d_in[8];
    const float* Wp     = (const float*)d_in[9];
    const float* bp     = (const float*)d_in[10];
    float* out = (float*)d_out;

    float *Wf, *bz, *zbuf, *gibuf, *cbuf;
    __nv_bfloat16 *predp, *zpb, *cpb, *wpsb;
    cudaGetSymbolAddress((void**)&Wf,    g_Wf);
    cudaGetSymbolAddress((void**)&bz,    g_bz);
    cudaGetSymbolAddress((void**)&zbuf,  g_z);
    cudaGetSymbolAddress((void**)&gibuf, g_gi);
    cudaGetSymbolAddress((void**)&cbuf,  g_c);
    cudaGetSymbolAddress((void**)&predp, g_predp);
    cudaGetSymbolAddress((void**)&zpb,   g_zp);
    cudaGetSymbolAddress((void**)&cpb,   g_cp);
    cudaGetSymbolAddress((void**)&wpsb,  g_wps);

    cudaFuncSetAttribute(gru_kernel,      cudaFuncAttributeMaxDynamicSharedMemorySize, GRU_SMEM_BYTES);
    cudaFuncSetAttribute(loss_mma_kernel, cudaFuncAttributeMaxDynamicSharedMemorySize, LOSS_SMEM_BYTES);
    cudaFuncSetAttribute(pred_mma_kernel, cudaFuncAttributeMaxDynamicSharedMemorySize, PRED_SMEM_BYTES);

    zero_loss_kernel<<<1, 32>>>(out);
    bz_kernel<<<1, 128>>>(b_enc, W_proj, b_proj, bz);

    // Wf = W_enc @ W_proj   (256x128x256)
    gemm_bias_kernel<<<dim3(1,2), 256>>>(W_enc, W_proj, nullptr, Wf, 256, 128, 256);
    // z = x @ Wf + bz       (32768x128x256)
    gemm_bias_kernel<<<dim3(1,256), 256>>>(x_seq, Wf, bz, zbuf, BT, NP, NF);
    // zp split pack
    zpack_kernel<<<(BT*NP+255)/256, 256>>>(zbuf, zpb);
    // gi = z @ Wi + bi      (32768x768x128)
    gemm_bias_kernel<<<dim3(6,256), 256>>>(zbuf, Wi, bi, gibuf, BT, 3*NH, NP);
    // Wp split repack (n-major)
    repack_wp_kernel<<<768, 512>>>(Wp, wpsb);
    // GRU scan (persistent, clustered)
    gru_kernel<<<128, 384, GRU_SMEM_BYTES>>>(gibuf, Wh, bhn, cbuf);
    // c split pack
    cpack_kernel<<<(BT*NH+255)/256, 256>>>(cbuf, cpb);
    // pred = c @ Wp + bp -> split-bf16 packed (tensor path)
    pred_mma_kernel<<<dim3(12,256), 256, PRED_SMEM_BYTES>>>(cpb, wpsb, bp, predp);
    // mma.sync streaming-softmax loss
    loss_mma_kernel<<<dim3(4,64,12), 256, LOSS_SMEM_BYTES>>>(predp, zpb, out);
}

// round 8
// speedup vs baseline: 1.3271x; 1.0154x over previous
#include <cuda_runtime.h>
#include <cuda_bf16.h>
#include <cstdint>
#include <math.h>

// Problem constants
#define NB 64
#define NT 512
#define NF 256
#define NP 128
#define NH 256
#define NK 12
#define INV_TEMP 10.0f
#define BT (NB*NT)   // 32768

// ---------------- device scratch (no allocations allowed) ---------------------
__device__ float g_Wf[NF*NP];                       // fused encoder weight 256x128
__device__ float g_bz[NP];                          // fused encoder bias
__device__ float g_z[(size_t)BT*NP];                // z_seq   (b,t,128)
__device__ float g_gi[(size_t)BT*3*NH];             // gi      (b,t,768)
__device__ __align__(16) __nv_bfloat16 g_predp[(size_t)BT*NK*256]; // pred split, pre-scaled
__device__ __align__(16) __nv_bfloat16 g_zp[(size_t)BT*256];       // z split [hi|lo]
__device__ __align__(16) __nv_bfloat16 g_cp[(size_t)BT*512];       // c split per-half [hi|lo]
__device__ __align__(16) __nv_bfloat16 g_wps[(size_t)2*1536*256];  // Wp split n-major
__device__ __align__(16) __nv_bfloat16 g_wis[(size_t)768*256];     // Wi split n-major

// ---------------- helpers -----------------------------------------------------
__device__ __forceinline__ unsigned smem_u32(const void* p){
    unsigned r;
    asm("{ .reg .u64 t; cvta.to.shared.u64 t, %1; cvt.u32.u64 %0, t; }" : "=r"(r) : "l"(p));
    return r;
}
__device__ __forceinline__ void cp_async16(uint32_t saddr, const void* gptr, uint32_t srcsz){
    asm volatile("cp.async.cg.shared.global [%0], [%1], 16, %2;"
                 :: "r"(saddr), "l"(gptr), "r"(srcsz));
}
#define CP_COMMIT() asm volatile("cp.async.commit_group;" ::: "memory")
#define CP_WAIT0()  asm volatile("cp.async.wait_group 0;" ::: "memory")

__global__ void zero_loss_kernel(float* p){ if (threadIdx.x==0) *p = 0.f; }

__global__ void bz_kernel(const float* __restrict__ b_enc, const float* __restrict__ W_proj,
                          const float* __restrict__ b_proj, float* __restrict__ bz){
    int n = threadIdx.x;            // 128
    float s = b_proj[n];
    for (int e = 0; e < NF; e++) s += b_enc[e] * W_proj[e*NP + n];
    bz[n] = s;
}

// Wp (12,256,128) -> wps[khalf][n=k*128+p][kr(256): hi|lo]
__global__ void repack_wp_kernel(const float* __restrict__ Wp, __nv_bfloat16* __restrict__ wps){
    int idx = blockIdx.x*blockDim.x + threadIdx.x;
    if (idx >= NK*NH*NP) return;
    int p = idx & 127;
    int h = (idx >> 7) & 255;
    int k = idx >> 15;
    float v = Wp[idx];
    __nv_bfloat16 hi = __float2bfloat16(v);
    __nv_bfloat16 lo = __float2bfloat16(v - __bfloat162float(hi));
    int n = k*128 + p;
    int khalf = h >> 7, kr = h & 127;
    size_t base = ((size_t)khalf*1536 + n)*256;
    wps[base + kr]       = hi;
    wps[base + 128 + kr] = lo;
}

// Wi (128,768) -> wis[n][kr(256): hi|lo]
__global__ void repack_wi_kernel(const float* __restrict__ Wi, __nv_bfloat16* __restrict__ wis){
    int idx = blockIdx.x*blockDim.x + threadIdx.x;    // 128*768
    if (idx >= 128*768) return;
    int n = idx % 768;
    int k = idx / 768;
    float v = Wi[idx];
    __nv_bfloat16 hi = __float2bfloat16(v);
    wis[(size_t)n*256 + k]       = hi;
    wis[(size_t)n*256 + 128 + k] = __float2bfloat16(v - __bfloat162float(hi));
}

// z fp32 -> split bf16 [hi(128)|lo(128)]
__global__ void zpack_kernel(const float* __restrict__ z, __nv_bfloat16* __restrict__ zp){
    int idx = blockIdx.x*blockDim.x + threadIdx.x;
    if (idx >= BT*NP) return;
    int row = idx >> 7, c = idx & 127;
    float v = z[idx];
    __nv_bfloat16 h = __float2bfloat16(v);
    zp[(size_t)row*256 + c]       = h;
    zp[(size_t)row*256 + 128 + c] = __float2bfloat16(v - __bfloat162float(h));
}

// ---------------- generic tiled GEMM: C = A(MxK) @ B(KxN) + bias --------------
__global__ void __launch_bounds__(256) gemm_bias_kernel(
    const float* __restrict__ A, const float* __restrict__ Bm,
    const float* __restrict__ bias, float* __restrict__ C,
    int M, int N, int K)
{
    __shared__ float As[16][128];
    __shared__ float Bs[16][128];
    const int tid = threadIdx.x;
    const int m0 = blockIdx.y * 128, n0 = blockIdx.x * 128;
    const int tx = tid & 15, ty = tid >> 4;
    float acc[8][8];
#pragma unroll
    for (int i=0;i<8;i++)
#pragma unroll
        for (int j=0;j<8;j++) acc[i][j] = 0.f;

    for (int k0 = 0; k0 < K; k0 += 16) {
#pragma unroll
        for (int it = 0; it < 2; it++) {
            int idx = tid + it*256;
            int r  = idx >> 2;
            int c4 = (idx & 3) << 2;
            const float4 v = *reinterpret_cast<const float4*>(A + (size_t)(m0+r)*K + k0 + c4);
            As[c4+0][r]=v.x; As[c4+1][r]=v.y; As[c4+2][r]=v.z; As[c4+3][r]=v.w;
        }
#pragma unroll
        for (int it = 0; it < 2; it++) {
            int idx = tid + it*256;
            int r  = idx >> 5;
            int c4 = (idx & 31) << 2;
            *reinterpret_cast<float4*>(&Bs[r][c4]) =
                *reinterpret_cast<const float4*>(Bm + (size_t)(k0+r)*N + n0 + c4);
        }
        __syncthreads();
#pragma unroll
        for (int k = 0; k < 16; k++) {
            float a[8], b[8];
            *reinterpret_cast<float4*>(&a[0]) = *reinterpret_cast<float4*>(&As[k][ty*4]);
            *reinterpret_cast<float4*>(&a[4]) = *reinterpret_cast<float4*>(&As[k][ty*4+64]);
            *reinterpret_cast<float4*>(&b[0]) = *reinterpret_cast<float4*>(&Bs[k][tx*4]);
            *reinterpret_cast<float4*>(&b[4]) = *reinterpret_cast<float4*>(&Bs[k][tx*4+64]);
#pragma unroll
            for (int i=0;i<8;i++)
#pragma unroll
                for (int j=0;j<8;j++) acc[i][j] += a[i]*b[j];
        }
        __syncthreads();
    }
#pragma unroll
    for (int i=0;i<8;i++){
        int m = m0 + ty*4 + (i&3) + ((i>>2)<<6);
#pragma unroll
        for (int jg=0;jg<2;jg++){
            int n = n0 + tx*4 + jg*64;
            float4 v;
            v.x = acc[i][jg*4+0]; v.y = acc[i][jg*4+1];
            v.z = acc[i][jg*4+2]; v.w = acc[i][jg*4+3];
            if (bias){
                const float4 bv = *reinterpret_cast<const float4*>(bias + n);
                v.x += bv.x; v.y += bv.y; v.z += bv.z; v.w += bv.w;
            }
            *reinterpret_cast<float4*>(C + (size_t)m*N + n) = v;
        }
    }
}

// ---------------- mma primitives ----------------------------------------------
__device__ __forceinline__ void ldmatrix_x4(uint32_t& r0, uint32_t& r1, uint32_t& r2, uint32_t& r3,
                                            uint32_t addr){
    asm volatile("ldmatrix.sync.aligned.m8n8.x4.shared.b16 {%0,%1,%2,%3}, [%4];"
        : "=r"(r0), "=r"(r1), "=r"(r2), "=r"(r3) : "r"(addr));
}
__device__ __forceinline__ void mma16816(float* d, const uint32_t* a, uint32_t b0, uint32_t b1){
    asm volatile("mma.sync.aligned.m16n8k16.row.col.f32.bf16.bf16.f32 "
        "{%0,%1,%2,%3}, {%4,%5,%6,%7}, {%8,%9}, {%0,%1,%2,%3};"
        : "+f"(d[0]), "+f"(d[1]), "+f"(d[2]), "+f"(d[3])
        : "r"(a[0]), "r"(a[1]), "r"(a[2]), "r"(a[3]), "r"(b0), "r"(b1));
}
__device__ __forceinline__ uint32_t pack2bf(__nv_bfloat16 a, __nv_bfloat16 b){
    __nv_bfloat162 t; t.x = a; t.y = b;
    return *reinterpret_cast<uint32_t*>(&t);
}

// ---------------- gi GEMM via mma.sync (3-term split bf16) --------------------
// gi = z @ Wi + bi. grid (6 n-tiles, 256 m-tiles), 256 threads. K=128 (256 packed).
#define PRS 264
#define GI_SMEM_BYTES (2*128*PRS*2)

__global__ void __launch_bounds__(256) gi_mma_kernel(
    const __nv_bfloat16* __restrict__ zp, const __nv_bfloat16* __restrict__ wis,
    const float* __restrict__ bi, float* __restrict__ gi)
{
    extern __shared__ __align__(16) char gsm[];
    __nv_bfloat16* SA = reinterpret_cast<__nv_bfloat16*>(gsm);
    __nv_bfloat16* SB = SA + 128*PRS;
    const uint32_t SAb = smem_u32(SA);
    const uint32_t SBb = smem_u32(SB);

    const int tid  = threadIdx.x;
    const int warp = tid >> 5;
    const int lane = tid & 31;
    const int n0   = blockIdx.x * 128;
    const int m0   = blockIdx.y * 128;

    // stage A (zp rows) and B (wis rows)
    for (int it = 0; it < 16; it++){
        int idx = tid + it*256;
        int r = idx >> 5, u = idx & 31;
        *reinterpret_cast<uint4*>(SA + r*PRS + u*8) =
            *reinterpret_cast<const uint4*>(zp + (size_t)(m0 + r)*256 + u*8);
        *reinterpret_cast<uint4*>(SB + r*PRS + u*8) =
            *reinterpret_cast<const uint4*>(wis + (size_t)(n0 + r)*256 + u*8);
    }
    __syncthreads();

    const uint32_t lrow = (lane & 7) + ((lane >> 3) & 1)*8;
    const uint32_t lcol = (lane >> 4)*8;
    const int mw = warp * 16;

    uint32_t afr[16][4];
#pragma unroll
    for (int kc = 0; kc < 16; kc++){
        uint32_t addr = SAb + ((mw + lrow)*PRS + kc*16 + lcol)*2;
        ldmatrix_x4(afr[kc][0], afr[kc][1], afr[kc][2], afr[kc][3], addr);
    }

    float acc[16][4];
#pragma unroll
    for (int nf = 0; nf < 16; nf++)
#pragma unroll
        for (int i = 0; i < 4; i++) acc[nf][i] = 0.f;

#pragma unroll
    for (int kc = 0; kc < 16; kc++){
#pragma unroll
        for (int nf2 = 0; nf2 < 8; nf2++){
            uint32_t r0,r1,r2,r3;
            uint32_t addr = SBb + ((nf2*16 + lrow)*PRS + kc*16 + lcol)*2;
            ldmatrix_x4(r0, r1, r2, r3, addr);
            if (kc < 8){
                mma16816(acc[nf2*2+0], afr[kc],   r0, r2);
                mma16816(acc[nf2*2+1], afr[kc],   r1, r3);
                mma16816(acc[nf2*2+0], afr[kc+8], r0, r2);
                mma16816(acc[nf2*2+1], afr[kc+8], r1, r3);
            } else {
                mma16816(acc[nf2*2+0], afr[kc-8], r0, r2);
                mma16816(acc[nf2*2+1], afr[kc-8], r1, r3);
            }
        }
    }

    const int r0g = m0 + mw + (lane >> 2);
#pragma unroll
    for (int nf = 0; nf < 16; nf++){
        int c0 = n0 + nf*8 + (lane & 3)*2;
        float b0 = bi[c0], b1 = bi[c0+1];
#pragma unroll
        for (int rr = 0; rr < 2; rr++){
            float2 v;
            v.x = acc[nf][rr*2+0] + b0;
            v.y = acc[nf][rr*2+1] + b1;
            *reinterpret_cast<float2*>(gi + (size_t)(r0g + rr*8)*768 + c0) = v;
        }
    }
}

// ---------------- pred GEMM via mma.sync (3-term, output pre-scaled) -----------
#define PRED_SMEM_BYTES (2*128*PRS*2)

__global__ void __launch_bounds__(256) pred_mma_kernel(
    const __nv_bfloat16* __restrict__ cp, const __nv_bfloat16* __restrict__ wps,
    const float* __restrict__ bp, __nv_bfloat16* __restrict__ predp)
{
    extern __shared__ __align__(16) char psm[];
    __nv_bfloat16* SA = reinterpret_cast<__nv_bfloat16*>(psm);
    __nv_bfloat16* SB = SA + 128*PRS;
    const uint32_t SAb = smem_u32(SA);
    const uint32_t SBb = smem_u32(SB);

    const int tid  = threadIdx.x;
    const int warp = tid >> 5;
    const int lane = tid & 31;
    const int kk   = blockIdx.x;
    const int m0   = blockIdx.y * 128;
    const int n0   = kk * 128;

    const uint32_t lrow = (lane & 7) + ((lane >> 3) & 1)*8;
    const uint32_t lcol = (lane >> 4)*8;
    const int mw = warp * 16;

    float acc[16][4];
#pragma unroll
    for (int nf = 0; nf < 16; nf++)
#pragma unroll
        for (int i = 0; i < 4; i++) acc[nf][i] = 0.f;

    for (int khalf = 0; khalf < 2; khalf++){
        for (int it = 0; it < 16; it++){
            int idx = tid + it*256;
            int r = idx >> 5, u = idx & 31;
            *reinterpret_cast<uint4*>(SA + r*PRS + u*8) =
                *reinterpret_cast<const uint4*>(cp + (size_t)(m0 + r)*512 + khalf*256 + u*8);
            *reinterpret_cast<uint4*>(SB + r*PRS + u*8) =
                *reinterpret_cast<const uint4*>(wps + ((size_t)khalf*1536 + n0 + r)*256 + u*8);
        }
        __syncthreads();

        uint32_t afr[16][4];
#pragma unroll
        for (int kc = 0; kc < 16; kc++){
            uint32_t addr = SAb + ((mw + lrow)*PRS + kc*16 + lcol)*2;
            ldmatrix_x4(afr[kc][0], afr[kc][1], afr[kc][2], afr[kc][3], addr);
        }

#pragma unroll
        for (int kc = 0; kc < 16; kc++){
#pragma unroll
            for (int nf2 = 0; nf2 < 8; nf2++){
                uint32_t r0,r1,r2,r3;
                uint32_t addr = SBb + ((nf2*16 + lrow)*PRS + kc*16 + lcol)*2;
                ldmatrix_x4(r0, r1, r2, r3, addr);
                if (kc < 8){
                    mma16816(acc[nf2*2+0], afr[kc],   r0, r2);
                    mma16816(acc[nf2*2+1], afr[kc],   r1, r3);
                    mma16816(acc[nf2*2+0], afr[kc+8], r0, r2);
                    mma16816(acc[nf2*2+1], afr[kc+8], r1, r3);
                } else {
                    mma16816(acc[nf2*2+0], afr[kc-8], r0, r2);
                    mma16816(acc[nf2*2+1], afr[kc-8], r1, r3);
                }
            }
        }
        __syncthreads();
    }

    const int r0g = m0 + mw + (lane >> 2);
    __nv_bfloat16* rp0 = predp + ((size_t)r0g*NK + kk)*256;
    __nv_bfloat16* rp1 = predp + ((size_t)(r0g+8)*NK + kk)*256;
#pragma unroll
    for (int nf = 0; nf < 16; nf++){
        int c0 = nf*8 + (lane & 3)*2;
        float b0 = bp[kk*128 + c0], b1 = bp[kk*128 + c0 + 1];
#pragma unroll
        for (int rr = 0; rr < 2; rr++){
            float v0 = (acc[nf][rr*2+0] + b0) * INV_TEMP;
            float v1 = (acc[nf][rr*2+1] + b1) * INV_TEMP;
            __nv_bfloat16 h0 = __float2bfloat16(v0);
            __nv_bfloat16 h1 = __float2bfloat16(v1);
            uint32_t hv = pack2bf(h0, h1);
            uint32_t lv = pack2bf(__float2bfloat16(v0 - __bfloat162float(h0)),
                                  __float2bfloat16(v1 - __bfloat162float(h1)));
            __nv_bfloat16* rp = rr ? rp1 : rp0;
            *reinterpret_cast<uint32_t*>(rp + c0)       = hv;
            *reinterpret_cast<uint32_t*>(rp + 128 + c0) = lv;
        }
    }
}

// ---------------- GRU scan (writes split-bf16 cp directly) --------------------
__device__ __forceinline__ void st_cluster_f32(unsigned laddr, int rank, float v){
    unsigned raddr;
    asm volatile("mapa.shared::cluster.u32 %0, %1, %2;" : "=r"(raddr) : "r"(laddr), "r"(rank));
    asm volatile("st.shared::cluster.f32 [%0], %1;" :: "r"(raddr), "f"(v) : "memory");
}
__device__ __forceinline__ void cluster_sync_all(){
    asm volatile("barrier.cluster.arrive.aligned;" ::: "memory");
    asm volatile("barrier.cluster.wait.aligned;"   ::: "memory");
}

#define GRU_SMEM_FLOATS 28576
#define GRU_SMEM_BYTES  (GRU_SMEM_FLOATS*4)

__global__ void __launch_bounds__(384) __cluster_dims__(8,1,1)
gru_kernel(const float* __restrict__ gi, const float* __restrict__ Wh,
           const float* __restrict__ bhn, __nv_bfloat16* __restrict__ cp_out)
{
    extern __shared__ float sm[];
    float* Whs   = sm;            // [256][96]
    float* h2    = sm + 24576;    // [2][256][4]
    float* part  = sm + 26624;    // [4][96][4]
    float* ghs   = sm + 28160;    // [4][96]
    float* bhn_s = sm + 28544;    // [32]

    const int tid  = threadIdx.x;
    const int rank = blockIdx.x & 7;
    const int b0   = (blockIdx.x >> 3) * 4;
    const int u0   = rank * 32;

    for (int i = tid; i < 256*96; i += 384){
        int u = i / 96, c = i % 96;
        int gcol = (c >> 5)*256 + u0 + (c & 31);
        Whs[i] = Wh[u*768 + gcol];
    }
    for (int i = tid; i < 2048; i += 384) h2[i] = 0.f;
    if (tid < 32) bhn_s[tid] = bhn[u0 + tid];
    __syncthreads();
    cluster_sync_all();

    const int c  = tid % 96;
    const int q  = tid / 96;
    const int b3 = tid >> 5;
    const int ul = tid & 31;

    int cur = 0;
    for (int t = 0; t < NT; t++){
        float gir=0.f, giz=0.f, gin=0.f;
        if (tid < 128){
            const float* gp = gi + ((size_t)(b0+b3)*NT + t)*768;
            gir = gp[u0+ul]; giz = gp[256+u0+ul]; gin = gp[512+u0+ul];
        }
        {
            const float* hb = h2 + cur*1024;
            float a0=0.f,a1=0.f,a2=0.f,a3=0.f;
            const int ub = q*64;
#pragma unroll 8
            for (int uu = 0; uu < 64; uu++){
                int u = ub + uu;
                float w = Whs[u*96 + c];
                float4 h4 = *reinterpret_cast<const float4*>(hb + u*4);
                a0 += w*h4.x; a1 += w*h4.y; a2 += w*h4.z; a3 += w*h4.w;
            }
            float* pp = part + (q*96 + c)*4;
            pp[0]=a0; pp[1]=a1; pp[2]=a2; pp[3]=a3;
        }
        __syncthreads();
        {
            int c2 = tid % 96, b2 = tid / 96;
            float s = part[(0*96+c2)*4+b2] + part[(1*96+c2)*4+b2]
                    + part[(2*96+c2)*4+b2] + part[(3*96+c2)*4+b2];
            ghs[b2*96 + c2] = s;
        }
        __syncthreads();

        int nxt = cur ^ 1;
        if (tid < 128){
            float hr = ghs[b3*96 + ul];
            float hz = ghs[b3*96 + 32 + ul];
            float hn = ghs[b3*96 + 64 + ul];
            float r  = 1.f/(1.f + expf(-(gir + hr)));
            float zz = 1.f/(1.f + expf(-(giz + hz)));
            float n  = tanhf(gin + r*(hn + bhn_s[ul]));
            float hp = h2[cur*1024 + (u0+ul)*4 + b3];
            float hnew = (1.f - zz)*n + zz*hp;
            // split-bf16 pack of c directly (replaces fp32 c buffer + cpack)
            int g = u0 + ul;
            size_t base = (((size_t)(b0+b3)*NT + t))*512 + (size_t)(g>>7)*256 + (g & 127);
            __nv_bfloat16 hh = __float2bfloat16(hnew);
            cp_out[base]       = hh;
            cp_out[base + 128] = __float2bfloat16(hnew - __bfloat162float(hh));
            unsigned laddr = smem_u32(h2 + nxt*1024 + (u0+ul)*4 + b3);
#pragma unroll
            for (int r8 = 0; r8 < 8; r8++) st_cluster_f32(laddr, r8, hnew);
        }
        cluster_sync_all();
        cur = nxt;
    }
}

// ---------------- mma.sync streaming-softmax contrastive loss -----------------
// A buffer + double-buffered Z (cp.async overlap). pred pre-scaled by INV_TEMP.
#define LOSS_RS 264
#define LOSS_TILE_BYTES (128*LOSS_RS*2)
#define LOSS_SMEM_BYTES (3*LOSS_TILE_BYTES)

__global__ void __launch_bounds__(256) loss_mma_kernel(
    const __nv_bfloat16* __restrict__ predp, const __nv_bfloat16* __restrict__ zp,
    float* __restrict__ out)
{
    extern __shared__ __align__(16) char lsm[];
    __nv_bfloat16* SA = reinterpret_cast<__nv_bfloat16*>(lsm);
    __nv_bfloat16* SZ0 = SA + 128*LOSS_RS;
    __nv_bfloat16* SZ1 = SZ0 + 128*LOSS_RS;
    const uint32_t SAb  = smem_u32(SA);
    const uint32_t SZb[2] = { smem_u32(SZ0), smem_u32(SZ1) };
    __shared__ float wsum[16];

    const int tid  = threadIdx.x;
    const int warp = tid >> 5;
    const int lane = tid & 31;
    const int b    = blockIdx.y;
    const int k    = blockIdx.z + 1;
    const int t0   = blockIdx.x * 128;
    const int Tm   = NT - k;

    // issue Z tile 0 via cp.async (overlaps A staging)
    {
        const int j0 = 0;
        for (int it = 0; it < 16; it++){
            int idx = tid + it*256;
            int j = idx >> 5, u = idx & 31;
            int jr = k + j0 + j;
            uint32_t ok = (jr < NT) ? 16u : 0u;
            int jc = jr < NT ? jr : NT-1;
            cp_async16(SZb[0] + (uint32_t)(j*LOSS_RS + u*8)*2,
                       zp + ((size_t)(b*NT) + jc)*256 + u*8, ok);
        }
        CP_COMMIT();
    }
    // stage A (pred rows, pre-scaled)
    for (int it = 0; it < 16; it++){
        int idx = tid + it*256;
        int r = idx >> 5, u = idx & 31;
        *reinterpret_cast<uint4*>(SA + r*LOSS_RS + u*8) =
            reinterpret_cast<const uint4*>(
                predp + (((size_t)(b*NT + t0 + r))*NK + (k-1))*256)[u];
    }
    __syncthreads();

    const int m0 = warp * 16;
    const uint32_t lrow = (lane & 7) + ((lane >> 3) & 1)*8;
    const uint32_t lcol = (lane >> 4)*8;
    uint32_t afr[16][4];
#pragma unroll
    for (int kc = 0; kc < 16; kc++){
        uint32_t addr = SAb + ((m0 + lrow)*LOSS_RS + kc*16 + lcol)*2;
        ldmatrix_x4(afr[kc][0], afr[kc][1], afr[kc][2], afr[kc][3], addr);
    }

    const int ra = t0 + m0 + (lane >> 2);
    const bool rv0 = ra < Tm, rv1 = (ra + 8) < Tm;
    float mr[2] = {-1e30f, -1e30f};
    float sr[2] = {0.f, 0.f};
    float tot = 0.f;

    for (int jt = 0; jt < 4; jt++){
        const int j0 = jt * 128;
        CP_WAIT0();
        __syncthreads();
        // prefetch next Z tile into the other buffer
        if (jt < 3){
            const int jn = (jt+1) * 128;
            const uint32_t dst = SZb[(jt+1) & 1];
            for (int it = 0; it < 16; it++){
                int idx = tid + it*256;
                int j = idx >> 5, u = idx & 31;
                int jr = k + jn + j;
                uint32_t ok = (jr < NT) ? 16u : 0u;
                int jc = jr < NT ? jr : NT-1;
                cp_async16(dst + (uint32_t)(j*LOSS_RS + u*8)*2,
                           zp + ((size_t)(b*NT) + jc)*256 + u*8, ok);
            }
            CP_COMMIT();
        }
        const uint32_t Zb = SZb[jt & 1];

        float acc[16][4];
#pragma unroll
        for (int nf = 0; nf < 16; nf++)
#pragma unroll
            for (int i = 0; i < 4; i++) acc[nf][i] = 0.f;

#pragma unroll
        for (int kc = 0; kc < 16; kc++){
#pragma unroll
            for (int nf2 = 0; nf2 < 8; nf2++){
                uint32_t r0,r1,r2,r3;
                uint32_t addr = Zb + (uint32_t)((nf2*16 + lrow)*LOSS_RS + kc*16 + lcol)*2;
                ldmatrix_x4(r0, r1, r2, r3, addr);
                if (kc < 8){
                    mma16816(acc[nf2*2+0], afr[kc],   r0, r2);
                    mma16816(acc[nf2*2+1], afr[kc],   r1, r3);
                    mma16816(acc[nf2*2+0], afr[kc+8], r0, r2);
                    mma16816(acc[nf2*2+1], afr[kc+8], r1, r3);
                } else {
                    mma16816(acc[nf2*2+0], afr[kc-8], r0, r2);
                    mma16816(acc[nf2*2+1], afr[kc-8], r1, r3);
                }
            }
        }

        // ---- epilogue (logits already scaled) ----
        if (j0 + 128 <= Tm){
            float tm[2] = {-1e30f, -1e30f};
#pragma unroll
            for (int nf = 0; nf < 16; nf++){
                tm[0] = fmaxf(tm[0], fmaxf(acc[nf][0], acc[nf][1]));
                tm[1] = fmaxf(tm[1], fmaxf(acc[nf][2], acc[nf][3]));
            }
#pragma unroll
            for (int o = 1; o <= 2; o <<= 1){
                tm[0] = fmaxf(tm[0], __shfl_xor_sync(0xFFFFFFFFu, tm[0], o));
                tm[1] = fmaxf(tm[1], __shfl_xor_sync(0xFFFFFFFFu, tm[1], o));
            }
#pragma unroll
            for (int rr = 0; rr < 2; rr++){
                float nm = fmaxf(mr[rr], tm[rr]);
                sr[rr] *= __expf(mr[rr] - nm);
                mr[rr] = nm;
            }
            float ls0 = 0.f, ls1 = 0.f, lt0 = 0.f, lt1 = 0.f;
#pragma unroll
            for (int nf = 0; nf < 16; nf++){
                ls0 += __expf(acc[nf][0] - mr[0]) + __expf(acc[nf][1] - mr[0]);
                ls1 += __expf(acc[nf][2] - mr[1]) + __expf(acc[nf][3] - mr[1]);
                lt0 += acc[nf][0] + acc[nf][1];
                lt1 += acc[nf][2] + acc[nf][3];
            }
            sr[0] += ls0; sr[1] += ls1;
            if (rv0) tot += lt0;
            if (rv1) tot += lt1;
        } else {
            const int cbase = j0 + (lane & 3)*2;
            float tm[2] = {-1e30f, -1e30f};
#pragma unroll
            for (int nf = 0; nf < 16; nf++){
                int c0 = cbase + nf*8;
                bool v0 = c0 < Tm, v1 = (c0+1) < Tm;
                if (v0){ tm[0] = fmaxf(tm[0], acc[nf][0]); tm[1] = fmaxf(tm[1], acc[nf][2]); }
                if (v1){ tm[0] = fmaxf(tm[0], acc[nf][1]); tm[1] = fmaxf(tm[1], acc[nf][3]); }
            }
#pragma unroll
            for (int o = 1; o <= 2; o <<= 1){
                tm[0] = fmaxf(tm[0], __shfl_xor_sync(0xFFFFFFFFu, tm[0], o));
                tm[1] = fmaxf(tm[1], __shfl_xor_sync(0xFFFFFFFFu, tm[1], o));
            }
            if (tm[0] > -1e29f){
#pragma unroll
                for (int rr = 0; rr < 2; rr++){
                    float nm = fmaxf(mr[rr], tm[rr]);
                    sr[rr] *= __expf(mr[rr] - nm);
                    mr[rr] = nm;
                }
                float ls0 = 0.f, ls1 = 0.f, lt0 = 0.f, lt1 = 0.f;
#pragma unroll
                for (int nf = 0; nf < 16; nf++){
                    int c0 = cbase + nf*8;
#pragma unroll
                    for (int h = 0; h < 2; h++){
                        if (c0 + h < Tm){
                            ls0 += __expf(acc[nf][h]   - mr[0]);
                            ls1 += __expf(acc[nf][2+h] - mr[1]);
                            lt0 += acc[nf][h]; lt1 += acc[nf][2+h];
                        }
                    }
                }
                sr[0] += ls0; sr[1] += ls1;
                if (rv0) tot += lt0;
                if (rv1) tot += lt1;
            }
        }
        __syncthreads();   // all warps done reading Zb before it is refilled
    }

    // ---- finalize ----
#pragma unroll
    for (int o = 1; o <= 2; o <<= 1){
        sr[0] += __shfl_xor_sync(0xFFFFFFFFu, sr[0], o);
        sr[1] += __shfl_xor_sync(0xFFFFFFFFu, sr[1], o);
    }
    float lse = 0.f;
    if ((lane & 3) == 0){
        if (rv0) lse += mr[0] + __logf(sr[0]);
        if (rv1) lse += mr[1] + __logf(sr[1]);
    }
#pragma unroll
    for (int o = 16; o; o >>= 1){
        lse += __shfl_xor_sync(0xFFFFFFFFu, lse, o);
        tot += __shfl_xor_sync(0xFFFFFFFFu, tot, o);
    }
    if (lane == 0){ wsum[warp] = lse; wsum[8+warp] = tot; }
    __syncthreads();
    if (tid == 0){
        float L = 0.f, T = 0.f;
#pragma unroll
        for (int w = 0; w < 8; w++){ L += wsum[w]; T += wsum[8+w]; }
        float inv = 1.0f / ((float)NB * (float)Tm * (float)NK);
        atomicAdd(out, L*inv - T*(inv/(float)Tm));
    }
}

// ---------------- launch ------------------------------------------------------
extern "C" void kernel_launch(void* const* d_in, const int* in_sizes, int n_in,
                              void* d_out, int out_size)
{
    const float* x_seq  = (const float*)d_in[0];
    const float* W_enc  = (const float*)d_in[1];
    const float* b_enc  = (const float*)d_in[2];
    const float* W_proj = (const float*)d_in[3];
    const float* b_proj = (const float*)d_in[4];
    const float* Wi     = (const float*)d_in[5];
    const float* bi     = (const float*)d_in[6];
    const float* Wh     = (const float*)d_in[7];
    const float* bhn    = (const float*)d_in[8];
    const float* Wp     = (const float*)d_in[9];
    const float* bp     = (const float*)d_in[10];
    float* out = (float*)d_out;

    float *Wf, *bz, *zbuf, *gibuf;
    __nv_bfloat16 *predp, *zpb, *cpb, *wpsb, *wisb;
    cudaGetSymbolAddress((void**)&Wf,    g_Wf);
    cudaGetSymbolAddress((void**)&bz,    g_bz);
    cudaGetSymbolAddress((void**)&zbuf,  g_z);
    cudaGetSymbolAddress((void**)&gibuf, g_gi);
    cudaGetSymbolAddress((void**)&predp, g_predp);
    cudaGetSymbolAddress((void**)&zpb,   g_zp);
    cudaGetSymbolAddress((void**)&cpb,   g_cp);
    cudaGetSymbolAddress((void**)&wpsb,  g_wps);
    cudaGetSymbolAddress((void**)&wisb,  g_wis);

    cudaFuncSetAttribute(gru_kernel,      cudaFuncAttributeMaxDynamicSharedMemorySize, GRU_SMEM_BYTES);
    cudaFuncSetAttribute(loss_mma_kernel, cudaFuncAttributeMaxDynamicSharedMemorySize, LOSS_SMEM_BYTES);
    cudaFuncSetAttribute(pred_mma_kernel, cudaFuncAttributeMaxDynamicSharedMemorySize, PRED_SMEM_BYTES);
    cudaFuncSetAttribute(gi_mma_kernel,   cudaFuncAttributeMaxDynamicSharedMemorySize, GI_SMEM_BYTES);

    zero_loss_kernel<<<1, 32>>>(out);
    bz_kernel<<<1, 128>>>(b_enc, W_proj, b_proj, bz);

    // Wf = W_enc @ W_proj   (256x128x256)
    gemm_bias_kernel<<<dim3(1,2), 256>>>(W_enc, W_proj, nullptr, Wf, 256, 128, 256);
    // z = x @ Wf + bz       (32768x128x256)
    gemm_bias_kernel<<<dim3(1,256), 256>>>(x_seq, Wf, bz, zbuf, BT, NP, NF);
    // zp split pack
    zpack_kernel<<<(BT*NP+255)/256, 256>>>(zbuf, zpb);
    // Wi split pack
    repack_wi_kernel<<<(128*768+255)/256, 256>>>(Wi, wisb);
    // gi = z @ Wi + bi  (tensor path)
    gi_mma_kernel<<<dim3(6,256), 256, GI_SMEM_BYTES>>>(zpb, wisb, bi, gibuf);
    // Wp split pack
    repack_wp_kernel<<<768, 512>>>(Wp, wpsb);
    // GRU scan (persistent, clustered; writes split c directly)
    gru_kernel<<<128, 384, GRU_SMEM_BYTES>>>(gibuf, Wh, bhn, cpb);
    // pred = (c @ Wp + bp)*INV_TEMP -> split-bf16 packed (tensor path)
    pred_mma_kernel<<<dim3(12,256), 256, PRED_SMEM_BYTES>>>(cpb, wpsb, bp, predp);
    // mma.sync streaming-softmax loss
    loss_mma_kernel<<<dim3(4,64,12), 256, LOSS_SMEM_BYTES>>>(predp, zpb, out);
}